// round 7
// baseline (speedup 1.0000x reference)
#include <cuda_runtime.h>
#include <math.h>
#include <stdint.h>

#define NTOK 2048

// ---------------- scratch ----------------
__device__ float g_xc [(size_t)4096 * 1024];       // x, tf32  [m][k]
__device__ float g_wqt[(size_t)1024 * 1024];       // Wq^T, tf32  [n][k]
__device__ float g_wkt[(size_t)256  * 1024];       // Wk^T
__device__ float g_wvt[(size_t)256  * 1024];       // Wv^T
__device__ float g_wot[(size_t)1024 * 1024];       // Wo^T
__device__ float g_q [(size_t)2 * 16 * NTOK * 64]; // [b][h][n][d]  tf32, q * (log2e/8)
__device__ float g_k [(size_t)2 * 4  * NTOK * 64]; // [b][kv][n][d] tf32
__device__ float g_vt[(size_t)2 * 4  * 64 * NTOK]; // [b][kv][d][n] tf32 (transposed)
__device__ float g_o [(size_t)4096 * 1024];        // [m][1024]     tf32

__device__ __forceinline__ float F2TF(float x) {
    uint32_t r; asm("cvt.rna.tf32.f32 %0, %1;" : "=r"(r) : "f"(x));
    return __uint_as_float(r);
}
__device__ __forceinline__ float EX2(float x) {
    float y; asm("ex2.approx.f32 %0, %1;" : "=f"(y) : "f"(x));
    return y;
}

__device__ __forceinline__ void mma8(float* d, float a0, float a1, float a2,
                                     float a3, float b0, float b1) {
    asm volatile(
        "mma.sync.aligned.m16n8k8.row.col.f32.tf32.tf32.f32 "
        "{%0,%1,%2,%3},{%4,%5,%6,%7},{%8,%9},{%0,%1,%2,%3};\n"
        : "+f"(d[0]), "+f"(d[1]), "+f"(d[2]), "+f"(d[3])
        : "r"(__float_as_uint(a0)), "r"(__float_as_uint(a1)),
          "r"(__float_as_uint(a2)), "r"(__float_as_uint(a3)),
          "r"(__float_as_uint(b0)), "r"(__float_as_uint(b1)));
}

#define CP_ASYNC16(dst, src) \
    asm volatile("cp.async.cg.shared.global [%0], [%1], 16;\n" :: "r"(dst), "l"(src))
#define CP_COMMIT() asm volatile("cp.async.commit_group;\n" ::: "memory")
#define CP_WAIT0()  asm volatile("cp.async.wait_group 0;\n" ::: "memory")
#define CP_WAIT1()  asm volatile("cp.async.wait_group 1;\n" ::: "memory")

// =============================================================================
// Prep A: x -> tf32 copy
// =============================================================================
__global__ __launch_bounds__(256) void cvtx_kernel(const float4* __restrict__ x)
{
    int i = blockIdx.x * 256 + threadIdx.x;   // 1048576 float4s
    float4 v = x[i];
    ((float4*)g_xc)[i] = make_float4(F2TF(v.x), F2TF(v.y), F2TF(v.z), F2TF(v.w));
}

// =============================================================================
// Prep B: weights -> tf32 + transpose to [n][k]  (32x32 smem tiles)
//   tiles: Wq 1024 | Wk 256 | Wv 256 | Wo 1024  => 2560 blocks
// =============================================================================
__global__ __launch_bounds__(256) void wtr_kernel(
    const float* __restrict__ wq, const float* __restrict__ wk,
    const float* __restrict__ wv, const float* __restrict__ wo)
{
    __shared__ float ts[32][33];
    int t = blockIdx.x;
    const float* src; float* dst; int N;
    if (t < 1024)      { src = wq; dst = g_wqt; N = 1024; }
    else if (t < 1280) { src = wk; dst = g_wkt; N = 256;  t -= 1024; }
    else if (t < 1536) { src = wv; dst = g_wvt; N = 256;  t -= 1280; }
    else               { src = wo; dst = g_wot; N = 1024; t -= 1536; }
    int tiles_n = N >> 5;
    int k0 = (t / tiles_n) << 5, n0 = (t % tiles_n) << 5;
    int tx = threadIdx.x & 31, ty = threadIdx.x >> 5;
    #pragma unroll
    for (int p = 0; p < 4; p++)
        ts[ty + p * 8][tx] = F2TF(src[(size_t)(k0 + ty + p * 8) * N + n0 + tx]);
    __syncthreads();
    #pragma unroll
    for (int p = 0; p < 4; p++)
        dst[(size_t)(n0 + ty + p * 8) * 1024 + k0 + tx] = ts[tx][ty + p * 8];
}

// =============================================================================
// GEMM mainloop: 128 threads / 4 warps, tile 128x64, k-step 32, 2-stage
// cp.async. A[m][k] pad36; B^T[n][k] pad36 (frags = float2, same pattern as A).
// =============================================================================
#define A_SZ (128 * 36)
#define B_SZ (64 * 36)
#define GEMM_SMEM ((2 * A_SZ + 2 * B_SZ) * 4)

__device__ __forceinline__ void gemm_mainloop(
    const float* __restrict__ Amat,
    const float* __restrict__ Bt,      // already offset: row n=0 is this block's col 0
    float* sm, int tid, int w, int g, int c, int m0,
    float acc[2][8][4])
{
    float* As = sm;
    float* Bs = sm + 2 * A_SZ;
    const uint32_t as_u = (uint32_t)__cvta_generic_to_shared(As);
    const uint32_t bs_u = (uint32_t)__cvta_generic_to_shared(Bs);

    const int aRow = tid >> 3, aCol = (tid & 7) * 4;   // 16 rows x 8 thr, 8 reps
    const int bRow = tid >> 3, bCol = (tid & 7) * 4;   // 16 rows x 8 thr, 4 reps

    {
        #pragma unroll
        for (int p = 0; p < 8; p++)
            CP_ASYNC16(as_u + ((p * 16 + aRow) * 36 + aCol) * 4,
                       &Amat[(size_t)(m0 + p * 16 + aRow) * 1024 + aCol]);
        #pragma unroll
        for (int p = 0; p < 4; p++)
            CP_ASYNC16(bs_u + ((p * 16 + bRow) * 36 + bCol) * 4,
                       &Bt[(size_t)(p * 16 + bRow) * 1024 + bCol]);
        CP_COMMIT();
    }

    for (int i = 0; i < 32; i++) {
        const int cur = i & 1;
        if (i + 1 < 32) {
            const int nxt = 1 - cur;
            const int k0 = (i + 1) * 32;
            #pragma unroll
            for (int p = 0; p < 8; p++)
                CP_ASYNC16(as_u + (nxt * A_SZ + (p * 16 + aRow) * 36 + aCol) * 4,
                           &Amat[(size_t)(m0 + p * 16 + aRow) * 1024 + k0 + aCol]);
            #pragma unroll
            for (int p = 0; p < 4; p++)
                CP_ASYNC16(bs_u + (nxt * B_SZ + (p * 16 + bRow) * 36 + bCol) * 4,
                           &Bt[(size_t)(p * 16 + bRow) * 1024 + k0 + bCol]);
            CP_COMMIT();
            CP_WAIT1();
        } else {
            CP_WAIT0();
        }
        __syncthreads();

        const float* Ac = As + cur * A_SZ;
        const float* Bc = Bs + cur * B_SZ;
        #pragma unroll
        for (int ks = 0; ks < 4; ks++) {
            float2 fa[4];
            #pragma unroll
            for (int r = 0; r < 4; r++)
                fa[r] = *(const float2*)&Ac[(w * 32 + r * 8 + g) * 36 + ks * 8 + 2 * c];
            #pragma unroll
            for (int nt = 0; nt < 8; nt++) {
                float2 wb = *(const float2*)&Bc[(nt * 8 + g) * 36 + ks * 8 + 2 * c];
                mma8(acc[0][nt], fa[0].x, fa[1].x, fa[0].y, fa[1].y, wb.x, wb.y);
                mma8(acc[1][nt], fa[2].x, fa[3].x, fa[2].y, fa[3].y, wb.x, wb.y);
            }
        }
        __syncthreads();
    }
}

// =============================================================================
// Kernel 1: QKV GEMM + bias + RMSNorm + 3D RoPE + q-scale (0.125*log2e)
// =============================================================================
__global__ __launch_bounds__(128) void qkv_kernel(
    const float* __restrict__ bq, const float* __restrict__ bk,
    const float* __restrict__ bv,
    const float* __restrict__ qn, const float* __restrict__ kn)
{
    extern __shared__ float sm[];
    const int tid = threadIdx.x;
    const int w = tid >> 5, lane = tid & 31, g = lane >> 2, c = lane & 3;
    const int m0 = blockIdx.y * 128;
    const int colb = blockIdx.x * 64;

    const float* Bt; const float* bias; int seg, colloc;
    if (colb < 1024)      { Bt = g_wqt; bias = bq; seg = 0; colloc = colb; }
    else if (colb < 1280) { Bt = g_wkt; bias = bk; seg = 1; colloc = colb - 1024; }
    else                  { Bt = g_wvt; bias = bv; seg = 2; colloc = colb - 1280; }

    float acc[2][8][4] = {};
    gemm_mainloop(g_xc, Bt + (size_t)colloc * 1024, sm, tid, w, g, c, m0, acc);

    #pragma unroll
    for (int nt = 0; nt < 8; nt++) {
        float b0v = bias[colloc + nt * 8 + 2 * c];
        float b1v = bias[colloc + nt * 8 + 2 * c + 1];
        #pragma unroll
        for (int mt = 0; mt < 2; mt++) {
            acc[mt][nt][0] += b0v; acc[mt][nt][1] += b1v;
            acc[mt][nt][2] += b0v; acc[mt][nt][3] += b1v;
        }
    }

    const int head = colloc >> 6;

    if (seg == 2) {
        #pragma unroll
        for (int mt = 0; mt < 2; mt++) {
            int m_a = m0 + w * 32 + mt * 16 + g;
            int b_ = m_a >> 11, n0 = m_a & 2047, n1 = n0 + 8;
            float* vb = &g_vt[((size_t)(b_ * 4 + head)) * 64 * NTOK];
            #pragma unroll
            for (int nt = 0; nt < 8; nt++) {
                int d0 = nt * 8 + 2 * c;
                vb[(size_t)d0 * NTOK + n0]       = F2TF(acc[mt][nt][0]);
                vb[(size_t)(d0 + 1) * NTOK + n0] = F2TF(acc[mt][nt][1]);
                vb[(size_t)d0 * NTOK + n1]       = F2TF(acc[mt][nt][2]);
                vb[(size_t)(d0 + 1) * NTOK + n1] = F2TF(acc[mt][nt][3]);
            }
        }
        return;
    }

    // RMSNorm (intra-warp over 64-wide head dim)
    const float* nw = (seg == 0) ? qn : kn;
    #pragma unroll
    for (int mt = 0; mt < 2; mt++) {
        float ss0 = 0.f, ss1 = 0.f;
        #pragma unroll
        for (int nt = 0; nt < 8; nt++) {
            ss0 += acc[mt][nt][0] * acc[mt][nt][0] + acc[mt][nt][1] * acc[mt][nt][1];
            ss1 += acc[mt][nt][2] * acc[mt][nt][2] + acc[mt][nt][3] * acc[mt][nt][3];
        }
        ss0 += __shfl_xor_sync(~0u, ss0, 1); ss0 += __shfl_xor_sync(~0u, ss0, 2);
        ss1 += __shfl_xor_sync(~0u, ss1, 1); ss1 += __shfl_xor_sync(~0u, ss1, 2);
        float rs0 = rsqrtf(ss0 * (1.f / 64.f) + 1e-6f);
        float rs1 = rsqrtf(ss1 * (1.f / 64.f) + 1e-6f);
        #pragma unroll
        for (int nt = 0; nt < 8; nt++) {
            float w0 = nw[nt * 8 + 2 * c], w1 = nw[nt * 8 + 2 * c + 1];
            acc[mt][nt][0] *= rs0 * w0; acc[mt][nt][1] *= rs0 * w1;
            acc[mt][nt][2] *= rs1 * w0; acc[mt][nt][3] *= rs1 * w1;
        }
    }

    // 3D RoPE in-place: pairs t:(0,1) h:(2,3) w:(4,6),(5,7)
    const int lo_[4] = {0, 2, 4, 5};
    const int hi_[4] = {1, 3, 6, 7};
    #pragma unroll
    for (int mt = 0; mt < 2; mt++) {
        int m_a = m0 + w * 32 + mt * 16 + g;
        int n0 = m_a & 2047, n1 = n0 + 8;
        float posr[2][3] = {
            {(float)(n0 >> 8), (float)((n0 >> 4) & 15), (float)(n0 & 15)},
            {(float)(n1 >> 8), (float)((n1 >> 4) & 15), (float)(n1 & 15)}};
        #pragma unroll
        for (int pi = 0; pi < 4; pi++) {
            int lo = lo_[pi], hi = hi_[pi];
            int ax = (pi == 0) ? 0 : (pi == 1 ? 1 : 2);
            float halfinv = (pi < 2) ? (1.f / 8.f) : (1.f / 16.f);
            #pragma unroll
            for (int e = 0; e < 2; e++) {
                float f = (pi < 2) ? (float)(2 * c + e)
                                   : (float)((lo & 1) * 8 + 2 * c + e);
                float inv = __powf(10000.f, -f * halfinv);
                #pragma unroll
                for (int r = 0; r < 2; r++) {
                    float sv, cv;
                    __sincosf(posr[r][ax] * inv, &sv, &cv);
                    float xl = acc[mt][lo][2 * r + e];
                    float xh = acc[mt][hi][2 * r + e];
                    acc[mt][lo][2 * r + e] = xl * cv - xh * sv;
                    acc[mt][hi][2 * r + e] = xh * cv + xl * sv;
                }
            }
        }
    }

    // q scale folds HD^-0.5 AND log2(e) (softmax exp done via ex2)
    float scale = (seg == 0) ? (0.125f * 1.4426950408889634f) : 1.f;
    #pragma unroll
    for (int mt = 0; mt < 2; mt++) {
        int m_a = m0 + w * 32 + mt * 16 + g;
        int b_ = m_a >> 11, n0 = m_a & 2047, n1 = n0 + 8;
        float* qb = (seg == 0) ? &g_q[((size_t)(b_ * 16 + head)) * NTOK * 64]
                               : &g_k[((size_t)(b_ * 4 + head)) * NTOK * 64];
        #pragma unroll
        for (int nt = 0; nt < 8; nt++) {
            int d0 = nt * 8 + 2 * c;
            *(float2*)&qb[(size_t)n0 * 64 + d0] =
                make_float2(F2TF(acc[mt][nt][0] * scale), F2TF(acc[mt][nt][1] * scale));
            *(float2*)&qb[(size_t)n1 * 64 + d0] =
                make_float2(F2TF(acc[mt][nt][2] * scale), F2TF(acc[mt][nt][3] * scale));
        }
    }
}

// =============================================================================
// Kernel 2: flash attention, no online max (scores bounded), ex2 softmax.
//   256 threads / 8 warps, warp M=16, q-block 128. K+V double-buffered,
//   one wait+sync per tile; next tile's K,V load entirely under compute.
// =============================================================================
#define KV_TILE (64 * 68)
#define ATTN_SMEM (4 * KV_TILE * 4)   // 2 bufs x (K + V)

__global__ __launch_bounds__(256, 2) void attn_kernel()
{
    extern __shared__ float sm[];     // [buf][K(4352) | V(4352)]

    const int tid = threadIdx.x;
    const int w = tid >> 5, lane = tid & 31, g = lane >> 2, c = lane & 3;
    const int q0 = blockIdx.x * 128;
    const int bh = blockIdx.y;
    const int b_ = bh >> 4, h = bh & 15, kv = h >> 2;

    const float* qg = &g_q[((size_t)(b_ * 16 + h)) * NTOK * 64];
    const float* kg = &g_k[((size_t)(b_ * 4 + kv)) * NTOK * 64];
    const float* vg = &g_vt[((size_t)(b_ * 4 + kv)) * 64 * NTOK];

    const int lr = tid >> 2, lc = (tid & 3) * 16;   // 64 rows, 4 thr x 4cp16
    const uint32_t k_u = (uint32_t)__cvta_generic_to_shared(sm) + (lr * 68 + lc) * 4;
    const uint32_t v_u = k_u + KV_TILE * 4;

    // Q fragments register-resident (rows q0+w*16+g, +8)
    float qf[8][4];
    {
        const float* r0 = &qg[(size_t)(q0 + w * 16 + g) * 64];
        #pragma unroll
        for (int ks = 0; ks < 8; ks++) {
            float2 a = *(const float2*)&r0[ks * 8 + 2 * c];
            float2 b = *(const float2*)&r0[8 * 64 + ks * 8 + 2 * c];
            qf[ks][0] = a.x; qf[ks][1] = b.x; qf[ks][2] = a.y; qf[ks][3] = b.y;
        }
    }

    float o[8][4] = {};
    float lp0 = 0.f, lp1 = 0.f;

    // prologue: K0, V0
    #pragma unroll
    for (int i = 0; i < 4; i++) {
        CP_ASYNC16(k_u + i * 16, &kg[(size_t)lr * 64 + lc + i * 4]);
        CP_ASYNC16(v_u + i * 16, &vg[(size_t)lr * NTOK + lc + i * 4]);
    }
    CP_COMMIT();

    for (int kt = 0; kt < NTOK; kt += 64) {
        const int buf = (kt >> 6) & 1;
        CP_WAIT0();
        __syncthreads();   // tile(t) ready; all warps done computing t-1

        if (kt + 64 < NTOK) {
            const uint32_t off = (1 - buf) * 2 * KV_TILE * 4;
            #pragma unroll
            for (int i = 0; i < 4; i++) {
                CP_ASYNC16(k_u + off + i * 16, &kg[(size_t)(kt + 64 + lr) * 64 + lc + i * 4]);
                CP_ASYNC16(v_u + off + i * 16, &vg[(size_t)lr * NTOK + kt + 64 + lc + i * 4]);
            }
            CP_COMMIT();
        }

        const float* Kc = sm + buf * 2 * KV_TILE;
        const float* Vc = Kc + KV_TILE;

        // S = Q K^T  (q carries log2e/8)
        float s[8][4] = {};
        #pragma unroll
        for (int ks = 0; ks < 8; ks++) {
            #pragma unroll
            for (int nt = 0; nt < 8; nt++) {
                float2 kb = *(const float2*)&Kc[(nt * 8 + g) * 68 + ks * 8 + 2 * c];
                mma8(s[nt], qf[ks][0], qf[ks][1], qf[ks][2], qf[ks][3], kb.x, kb.y);
            }
        }

        // p = 2^s (bounded, no max shift) + partial row sums
        #pragma unroll
        for (int nt = 0; nt < 8; nt++) {
            s[nt][0] = EX2(s[nt][0]); s[nt][1] = EX2(s[nt][1]);
            s[nt][2] = EX2(s[nt][2]); s[nt][3] = EX2(s[nt][3]);
            lp0 += s[nt][0] + s[nt][1];
            lp1 += s[nt][2] + s[nt][3];
        }

        // O += P V (S accumulator reused as A fragment)
        #pragma unroll
        for (int ks = 0; ks < 8; ks++) {
            float a0 = F2TF(s[ks][0]);
            float a1 = F2TF(s[ks][2]);
            float a2 = F2TF(s[ks][1]);
            float a3 = F2TF(s[ks][3]);
            #pragma unroll
            for (int nt = 0; nt < 8; nt++) {
                float2 vb = *(const float2*)&Vc[(nt * 8 + g) * 68 + ks * 8 + 2 * c];
                mma8(o[nt], a0, a1, a2, a3, vb.x, vb.y);
            }
        }
    }

    lp0 += __shfl_xor_sync(~0u, lp0, 1); lp0 += __shfl_xor_sync(~0u, lp0, 2);
    lp1 += __shfl_xor_sync(~0u, lp1, 1); lp1 += __shfl_xor_sync(~0u, lp1, 2);
    float inv0 = 1.f / lp0, inv1 = 1.f / lp1;

    int n0 = q0 + w * 16 + g, n1 = n0 + 8;
    float* ob0 = &g_o[((size_t)(b_ * NTOK + n0)) * 1024 + h * 64];
    float* ob1 = &g_o[((size_t)(b_ * NTOK + n1)) * 1024 + h * 64];
    #pragma unroll
    for (int nt = 0; nt < 8; nt++) {
        int d0 = nt * 8 + 2 * c;
        *(float2*)&ob0[d0] = make_float2(F2TF(o[nt][0] * inv0), F2TF(o[nt][1] * inv0));
        *(float2*)&ob1[d0] = make_float2(F2TF(o[nt][2] * inv1), F2TF(o[nt][3] * inv1));
    }
}

// =============================================================================
// Kernel 3: out = O @ Wo + bo
// =============================================================================
__global__ __launch_bounds__(128) void out_kernel(
    const float* __restrict__ bo, float* __restrict__ out)
{
    extern __shared__ float sm[];
    const int tid = threadIdx.x;
    const int w = tid >> 5, lane = tid & 31, g = lane >> 2, c = lane & 3;
    const int m0 = blockIdx.y * 128;
    const int colb = blockIdx.x * 64;

    float acc[2][8][4] = {};
    gemm_mainloop(g_o, g_wot + (size_t)colb * 1024, sm, tid, w, g, c, m0, acc);

    #pragma unroll
    for (int mt = 0; mt < 2; mt++) {
        int m_a = m0 + w * 32 + mt * 16 + g;
        float* r0 = &out[(size_t)m_a * 1024 + colb];
        float* r1 = &out[(size_t)(m_a + 8) * 1024 + colb];
        #pragma unroll
        for (int nt = 0; nt < 8; nt++) {
            int d0 = nt * 8 + 2 * c;
            float b0v = bo[colb + d0], b1v = bo[colb + d0 + 1];
            *(float2*)&r0[d0] = make_float2(acc[mt][nt][0] + b0v, acc[mt][nt][1] + b1v);
            *(float2*)&r1[d0] = make_float2(acc[mt][nt][2] + b0v, acc[mt][nt][3] + b1v);
        }
    }
}

// =============================================================================
extern "C" void kernel_launch(void* const* d_in, const int* in_sizes, int n_in,
                              void* d_out, int out_size)
{
    const float* x  = (const float*)d_in[0];
    const float* Wq = (const float*)d_in[1];
    const float* bq = (const float*)d_in[2];
    const float* Wk = (const float*)d_in[3];
    const float* bk = (const float*)d_in[4];
    const float* Wv = (const float*)d_in[5];
    const float* bv = (const float*)d_in[6];
    const float* Wo = (const float*)d_in[7];
    const float* bo = (const float*)d_in[8];
    const float* qn = (const float*)d_in[9];
    const float* kn = (const float*)d_in[10];
    float* out = (float*)d_out;

    cudaFuncSetAttribute(qkv_kernel, cudaFuncAttributeMaxDynamicSharedMemorySize, GEMM_SMEM);
    cudaFuncSetAttribute(out_kernel, cudaFuncAttributeMaxDynamicSharedMemorySize, GEMM_SMEM);
    cudaFuncSetAttribute(attn_kernel, cudaFuncAttributeMaxDynamicSharedMemorySize, ATTN_SMEM);

    cvtx_kernel<<<4096, 256>>>((const float4*)x);
    wtr_kernel<<<2560, 256>>>(Wq, Wk, Wv, Wo);
    qkv_kernel<<<dim3(24, 32), 128, GEMM_SMEM>>>(bq, bk, bv, qn, kn);
    attn_kernel<<<dim3(16, 32), 256, ATTN_SMEM>>>();
    out_kernel<<<dim3(16, 32), 128, GEMM_SMEM>>>(bo, out);
}

// round 8
// speedup vs baseline: 1.0546x; 1.0546x over previous
#include <cuda_runtime.h>
#include <math.h>
#include <stdint.h>

#define NTOK 2048

// ---------------- scratch ----------------
__device__ float g_xc [(size_t)4096 * 1024];       // x, tf32  [m][k]
__device__ float g_wqt[(size_t)1024 * 1024];       // Wq^T, tf32  [n][k]
__device__ float g_wkt[(size_t)256  * 1024];       // Wk^T
__device__ float g_wvt[(size_t)256  * 1024];       // Wv^T
__device__ float g_wot[(size_t)1024 * 1024];       // Wo^T
__device__ float g_q [(size_t)2 * 16 * NTOK * 64]; // [b][h][n][d]  tf32, q * (log2e/8)
__device__ float g_k [(size_t)2 * 4  * NTOK * 64]; // [b][kv][n][d] tf32
__device__ float g_vt[(size_t)2 * 4  * 64 * NTOK]; // [b][kv][d][n] tf32 (transposed)
__device__ float g_o [(size_t)4096 * 1024];        // [m][1024]     tf32

__device__ __forceinline__ float F2TF(float x) {
    uint32_t r; asm("cvt.rna.tf32.f32 %0, %1;" : "=r"(r) : "f"(x));
    return __uint_as_float(r);
}
__device__ __forceinline__ float EX2(float x) {
    float y; asm("ex2.approx.f32 %0, %1;" : "=f"(y) : "f"(x));
    return y;
}

__device__ __forceinline__ void mma8(float* d, float a0, float a1, float a2,
                                     float a3, float b0, float b1) {
    asm volatile(
        "mma.sync.aligned.m16n8k8.row.col.f32.tf32.tf32.f32 "
        "{%0,%1,%2,%3},{%4,%5,%6,%7},{%8,%9},{%0,%1,%2,%3};\n"
        : "+f"(d[0]), "+f"(d[1]), "+f"(d[2]), "+f"(d[3])
        : "r"(__float_as_uint(a0)), "r"(__float_as_uint(a1)),
          "r"(__float_as_uint(a2)), "r"(__float_as_uint(a3)),
          "r"(__float_as_uint(b0)), "r"(__float_as_uint(b1)));
}

#define CP_ASYNC16(dst, src) \
    asm volatile("cp.async.cg.shared.global [%0], [%1], 16;\n" :: "r"(dst), "l"(src))
#define CP_COMMIT() asm volatile("cp.async.commit_group;\n" ::: "memory")
#define CP_WAIT0()  asm volatile("cp.async.wait_group 0;\n" ::: "memory")
#define CP_WAIT1()  asm volatile("cp.async.wait_group 1;\n" ::: "memory")

// =============================================================================
// Prep A: x -> tf32 copy
// =============================================================================
__global__ __launch_bounds__(256) void cvtx_kernel(const float4* __restrict__ x)
{
    int i = blockIdx.x * 256 + threadIdx.x;   // 1048576 float4s
    float4 v = x[i];
    ((float4*)g_xc)[i] = make_float4(F2TF(v.x), F2TF(v.y), F2TF(v.z), F2TF(v.w));
}

// =============================================================================
// Prep B: weights -> tf32 + transpose to [n][k]  (32x32 smem tiles)
// =============================================================================
__global__ __launch_bounds__(256) void wtr_kernel(
    const float* __restrict__ wq, const float* __restrict__ wk,
    const float* __restrict__ wv, const float* __restrict__ wo)
{
    __shared__ float ts[32][33];
    int t = blockIdx.x;
    const float* src; float* dst; int N;
    if (t < 1024)      { src = wq; dst = g_wqt; N = 1024; }
    else if (t < 1280) { src = wk; dst = g_wkt; N = 256;  t -= 1024; }
    else if (t < 1536) { src = wv; dst = g_wvt; N = 256;  t -= 1280; }
    else               { src = wo; dst = g_wot; N = 1024; t -= 1536; }
    int tiles_n = N >> 5;
    int k0 = (t / tiles_n) << 5, n0 = (t % tiles_n) << 5;
    int tx = threadIdx.x & 31, ty = threadIdx.x >> 5;
    #pragma unroll
    for (int p = 0; p < 4; p++)
        ts[ty + p * 8][tx] = F2TF(src[(size_t)(k0 + ty + p * 8) * N + n0 + tx]);
    __syncthreads();
    #pragma unroll
    for (int p = 0; p < 4; p++)
        dst[(size_t)(n0 + ty + p * 8) * 1024 + k0 + tx] = ts[tx][ty + p * 8];
}

// =============================================================================
// GEMM mainloop: 128 threads / 4 warps, tile 128x64, k-step 32, 2-stage
// cp.async. A[m][k] pad36; B^T[n][k] pad36 (frags = float2).
// =============================================================================
#define A_SZ (128 * 36)
#define B_SZ (64 * 36)
#define GEMM_SMEM ((2 * A_SZ + 2 * B_SZ) * 4)

__device__ __forceinline__ void gemm_mainloop(
    const float* __restrict__ Amat,
    const float* __restrict__ Bt,
    float* sm, int tid, int w, int g, int c, int m0,
    float acc[2][8][4])
{
    float* As = sm;
    float* Bs = sm + 2 * A_SZ;
    const uint32_t as_u = (uint32_t)__cvta_generic_to_shared(As);
    const uint32_t bs_u = (uint32_t)__cvta_generic_to_shared(Bs);

    const int aRow = tid >> 3, aCol = (tid & 7) * 4;
    const int bRow = tid >> 3, bCol = (tid & 7) * 4;

    {
        #pragma unroll
        for (int p = 0; p < 8; p++)
            CP_ASYNC16(as_u + ((p * 16 + aRow) * 36 + aCol) * 4,
                       &Amat[(size_t)(m0 + p * 16 + aRow) * 1024 + aCol]);
        #pragma unroll
        for (int p = 0; p < 4; p++)
            CP_ASYNC16(bs_u + ((p * 16 + bRow) * 36 + bCol) * 4,
                       &Bt[(size_t)(p * 16 + bRow) * 1024 + bCol]);
        CP_COMMIT();
    }

    for (int i = 0; i < 32; i++) {
        const int cur = i & 1;
        if (i + 1 < 32) {
            const int nxt = 1 - cur;
            const int k0 = (i + 1) * 32;
            #pragma unroll
            for (int p = 0; p < 8; p++)
                CP_ASYNC16(as_u + (nxt * A_SZ + (p * 16 + aRow) * 36 + aCol) * 4,
                           &Amat[(size_t)(m0 + p * 16 + aRow) * 1024 + k0 + aCol]);
            #pragma unroll
            for (int p = 0; p < 4; p++)
                CP_ASYNC16(bs_u + (nxt * B_SZ + (p * 16 + bRow) * 36 + bCol) * 4,
                           &Bt[(size_t)(p * 16 + bRow) * 1024 + k0 + bCol]);
            CP_COMMIT();
            CP_WAIT1();
        } else {
            CP_WAIT0();
        }
        __syncthreads();

        const float* Ac = As + cur * A_SZ;
        const float* Bc = Bs + cur * B_SZ;
        #pragma unroll
        for (int ks = 0; ks < 4; ks++) {
            float2 fa[4];
            #pragma unroll
            for (int r = 0; r < 4; r++)
                fa[r] = *(const float2*)&Ac[(w * 32 + r * 8 + g) * 36 + ks * 8 + 2 * c];
            #pragma unroll
            for (int nt = 0; nt < 8; nt++) {
                float2 wb = *(const float2*)&Bc[(nt * 8 + g) * 36 + ks * 8 + 2 * c];
                mma8(acc[0][nt], fa[0].x, fa[1].x, fa[0].y, fa[1].y, wb.x, wb.y);
                mma8(acc[1][nt], fa[2].x, fa[3].x, fa[2].y, fa[3].y, wb.x, wb.y);
            }
        }
        __syncthreads();
    }
}

// =============================================================================
// Kernel 1: QKV GEMM + bias + RMSNorm + 3D RoPE + q-scale (0.125*log2e)
// =============================================================================
__global__ __launch_bounds__(128) void qkv_kernel(
    const float* __restrict__ bq, const float* __restrict__ bk,
    const float* __restrict__ bv,
    const float* __restrict__ qn, const float* __restrict__ kn)
{
    extern __shared__ float sm[];
    const int tid = threadIdx.x;
    const int w = tid >> 5, lane = tid & 31, g = lane >> 2, c = lane & 3;
    const int m0 = blockIdx.y * 128;
    const int colb = blockIdx.x * 64;

    const float* Bt; const float* bias; int seg, colloc;
    if (colb < 1024)      { Bt = g_wqt; bias = bq; seg = 0; colloc = colb; }
    else if (colb < 1280) { Bt = g_wkt; bias = bk; seg = 1; colloc = colb - 1024; }
    else                  { Bt = g_wvt; bias = bv; seg = 2; colloc = colb - 1280; }

    float acc[2][8][4] = {};
    gemm_mainloop(g_xc, Bt + (size_t)colloc * 1024, sm, tid, w, g, c, m0, acc);

    #pragma unroll
    for (int nt = 0; nt < 8; nt++) {
        float b0v = bias[colloc + nt * 8 + 2 * c];
        float b1v = bias[colloc + nt * 8 + 2 * c + 1];
        #pragma unroll
        for (int mt = 0; mt < 2; mt++) {
            acc[mt][nt][0] += b0v; acc[mt][nt][1] += b1v;
            acc[mt][nt][2] += b0v; acc[mt][nt][3] += b1v;
        }
    }

    const int head = colloc >> 6;

    if (seg == 2) {
        #pragma unroll
        for (int mt = 0; mt < 2; mt++) {
            int m_a = m0 + w * 32 + mt * 16 + g;
            int b_ = m_a >> 11, n0 = m_a & 2047, n1 = n0 + 8;
            float* vb = &g_vt[((size_t)(b_ * 4 + head)) * 64 * NTOK];
            #pragma unroll
            for (int nt = 0; nt < 8; nt++) {
                int d0 = nt * 8 + 2 * c;
                vb[(size_t)d0 * NTOK + n0]       = F2TF(acc[mt][nt][0]);
                vb[(size_t)(d0 + 1) * NTOK + n0] = F2TF(acc[mt][nt][1]);
                vb[(size_t)d0 * NTOK + n1]       = F2TF(acc[mt][nt][2]);
                vb[(size_t)(d0 + 1) * NTOK + n1] = F2TF(acc[mt][nt][3]);
            }
        }
        return;
    }

    // RMSNorm (intra-warp over 64-wide head dim)
    const float* nw = (seg == 0) ? qn : kn;
    #pragma unroll
    for (int mt = 0; mt < 2; mt++) {
        float ss0 = 0.f, ss1 = 0.f;
        #pragma unroll
        for (int nt = 0; nt < 8; nt++) {
            ss0 += acc[mt][nt][0] * acc[mt][nt][0] + acc[mt][nt][1] * acc[mt][nt][1];
            ss1 += acc[mt][nt][2] * acc[mt][nt][2] + acc[mt][nt][3] * acc[mt][nt][3];
        }
        ss0 += __shfl_xor_sync(~0u, ss0, 1); ss0 += __shfl_xor_sync(~0u, ss0, 2);
        ss1 += __shfl_xor_sync(~0u, ss1, 1); ss1 += __shfl_xor_sync(~0u, ss1, 2);
        float rs0 = rsqrtf(ss0 * (1.f / 64.f) + 1e-6f);
        float rs1 = rsqrtf(ss1 * (1.f / 64.f) + 1e-6f);
        #pragma unroll
        for (int nt = 0; nt < 8; nt++) {
            float w0 = nw[nt * 8 + 2 * c], w1 = nw[nt * 8 + 2 * c + 1];
            acc[mt][nt][0] *= rs0 * w0; acc[mt][nt][1] *= rs0 * w1;
            acc[mt][nt][2] *= rs1 * w0; acc[mt][nt][3] *= rs1 * w1;
        }
    }

    // 3D RoPE in-place: pairs t:(0,1) h:(2,3) w:(4,6),(5,7)
    const int lo_[4] = {0, 2, 4, 5};
    const int hi_[4] = {1, 3, 6, 7};
    #pragma unroll
    for (int mt = 0; mt < 2; mt++) {
        int m_a = m0 + w * 32 + mt * 16 + g;
        int n0 = m_a & 2047, n1 = n0 + 8;
        float posr[2][3] = {
            {(float)(n0 >> 8), (float)((n0 >> 4) & 15), (float)(n0 & 15)},
            {(float)(n1 >> 8), (float)((n1 >> 4) & 15), (float)(n1 & 15)}};
        #pragma unroll
        for (int pi = 0; pi < 4; pi++) {
            int lo = lo_[pi], hi = hi_[pi];
            int ax = (pi == 0) ? 0 : (pi == 1 ? 1 : 2);
            float halfinv = (pi < 2) ? (1.f / 8.f) : (1.f / 16.f);
            #pragma unroll
            for (int e = 0; e < 2; e++) {
                float f = (pi < 2) ? (float)(2 * c + e)
                                   : (float)((lo & 1) * 8 + 2 * c + e);
                float inv = __powf(10000.f, -f * halfinv);
                #pragma unroll
                for (int r = 0; r < 2; r++) {
                    float sv, cv;
                    __sincosf(posr[r][ax] * inv, &sv, &cv);
                    float xl = acc[mt][lo][2 * r + e];
                    float xh = acc[mt][hi][2 * r + e];
                    acc[mt][lo][2 * r + e] = xl * cv - xh * sv;
                    acc[mt][hi][2 * r + e] = xh * cv + xl * sv;
                }
            }
        }
    }

    // q scale folds HD^-0.5 AND log2(e) (softmax exp via ex2)
    float scale = (seg == 0) ? (0.125f * 1.4426950408889634f) : 1.f;
    #pragma unroll
    for (int mt = 0; mt < 2; mt++) {
        int m_a = m0 + w * 32 + mt * 16 + g;
        int b_ = m_a >> 11, n0 = m_a & 2047, n1 = n0 + 8;
        float* qb = (seg == 0) ? &g_q[((size_t)(b_ * 16 + head)) * NTOK * 64]
                               : &g_k[((size_t)(b_ * 4 + head)) * NTOK * 64];
        #pragma unroll
        for (int nt = 0; nt < 8; nt++) {
            int d0 = nt * 8 + 2 * c;
            *(float2*)&qb[(size_t)n0 * 64 + d0] =
                make_float2(F2TF(acc[mt][nt][0] * scale), F2TF(acc[mt][nt][1] * scale));
            *(float2*)&qb[(size_t)n1 * 64 + d0] =
                make_float2(F2TF(acc[mt][nt][2] * scale), F2TF(acc[mt][nt][3] * scale));
        }
    }
}

// =============================================================================
// Kernel 2: flash attention. 128 threads / 4 warps, warp M=32 (each K/V frag
//   feeds 2 mmas), q-block 128. K+V double-buffered, ONE wait+sync per tile.
//   No online max (scores bounded); ex2 softmax (log2e folded into q).
// =============================================================================
#define KV_TILE (64 * 68)
#define ATTN_SMEM (4 * KV_TILE * 4)   // 2 bufs x (K + V)

__global__ __launch_bounds__(128) void attn_kernel()
{
    extern __shared__ float sm[];     // [buf][ K(4352) | V(4352) ]

    const int tid = threadIdx.x;
    const int w = tid >> 5, lane = tid & 31, g = lane >> 2, c = lane & 3;
    const int q0 = blockIdx.x * 128;
    const int bh = blockIdx.y;
    const int b_ = bh >> 4, h = bh & 15, kv = h >> 2;

    const float* qg = &g_q[((size_t)(b_ * 16 + h)) * NTOK * 64];
    const float* kg = &g_k[((size_t)(b_ * 4 + kv)) * NTOK * 64];
    const float* vg = &g_vt[((size_t)(b_ * 4 + kv)) * 64 * NTOK];

    // loaders: 128 threads; row = tid>>1 (0..63), half-row = (tid&1)*32
    const int lr = tid >> 1, lc = (tid & 1) * 32;
    const uint32_t k_u = (uint32_t)__cvta_generic_to_shared(sm) + (lr * 68 + lc) * 4;
    const uint32_t v_u = k_u + KV_TILE * 4;

    // Q fragments register-resident: rows w*32+g {+0,+8} (mt0), {+16,+24} (mt1)
    float qf[2][8][4];
    {
        const float* r0 = &qg[(size_t)(q0 + w * 32 + g) * 64];
        #pragma unroll
        for (int ks = 0; ks < 8; ks++) {
            float2 a = *(const float2*)&r0[ks * 8 + 2 * c];
            float2 b = *(const float2*)&r0[8 * 64 + ks * 8 + 2 * c];
            float2 d = *(const float2*)&r0[16 * 64 + ks * 8 + 2 * c];
            float2 e = *(const float2*)&r0[24 * 64 + ks * 8 + 2 * c];
            qf[0][ks][0] = a.x; qf[0][ks][1] = b.x; qf[0][ks][2] = a.y; qf[0][ks][3] = b.y;
            qf[1][ks][0] = d.x; qf[1][ks][1] = e.x; qf[1][ks][2] = d.y; qf[1][ks][3] = e.y;
        }
    }

    float o[2][8][4] = {};
    float lp[4] = {0.f, 0.f, 0.f, 0.f};

    // prologue: K0 + V0
    #pragma unroll
    for (int i = 0; i < 8; i++) {
        CP_ASYNC16(k_u + i * 16, &kg[(size_t)lr * 64 + lc + i * 4]);
        CP_ASYNC16(v_u + i * 16, &vg[(size_t)lr * NTOK + lc + i * 4]);
    }
    CP_COMMIT();

    for (int kt = 0; kt < NTOK; kt += 64) {
        const int buf = (kt >> 6) & 1;
        CP_WAIT0();
        __syncthreads();   // tile(t) resident; all warps done with tile(t-1)

        if (kt + 64 < NTOK) {   // load tile(t+1) into other buffer, under compute
            const uint32_t off = (1 - buf) * 2 * KV_TILE * 4;
            #pragma unroll
            for (int i = 0; i < 8; i++) {
                CP_ASYNC16(k_u + off + i * 16, &kg[(size_t)(kt + 64 + lr) * 64 + lc + i * 4]);
                CP_ASYNC16(v_u + off + i * 16, &vg[(size_t)lr * NTOK + kt + 64 + lc + i * 4]);
            }
            CP_COMMIT();
        }

        const float* Kc = sm + buf * 2 * KV_TILE;
        const float* Vc = Kc + KV_TILE;

        // S = Q K^T  (each K frag feeds both mt halves)
        float s[2][8][4] = {};
        #pragma unroll
        for (int ks = 0; ks < 8; ks++) {
            #pragma unroll
            for (int nt = 0; nt < 8; nt++) {
                float2 kb = *(const float2*)&Kc[(nt * 8 + g) * 68 + ks * 8 + 2 * c];
                mma8(s[0][nt], qf[0][ks][0], qf[0][ks][1], qf[0][ks][2], qf[0][ks][3], kb.x, kb.y);
                mma8(s[1][nt], qf[1][ks][0], qf[1][ks][1], qf[1][ks][2], qf[1][ks][3], kb.x, kb.y);
            }
        }

        // p = 2^s (bounded; no max shift) + partial row sums
        #pragma unroll
        for (int mt = 0; mt < 2; mt++)
            #pragma unroll
            for (int nt = 0; nt < 8; nt++) {
                s[mt][nt][0] = EX2(s[mt][nt][0]); s[mt][nt][1] = EX2(s[mt][nt][1]);
                s[mt][nt][2] = EX2(s[mt][nt][2]); s[mt][nt][3] = EX2(s[mt][nt][3]);
                lp[2 * mt]     += s[mt][nt][0] + s[mt][nt][1];
                lp[2 * mt + 1] += s[mt][nt][2] + s[mt][nt][3];
            }

        // O += P V  (S accumulators reused as A frags; V frag feeds both mt)
        #pragma unroll
        for (int ks = 0; ks < 8; ks++) {
            float a00 = F2TF(s[0][ks][0]), a01 = F2TF(s[0][ks][2]);
            float a02 = F2TF(s[0][ks][1]), a03 = F2TF(s[0][ks][3]);
            float a10 = F2TF(s[1][ks][0]), a11 = F2TF(s[1][ks][2]);
            float a12 = F2TF(s[1][ks][1]), a13 = F2TF(s[1][ks][3]);
            #pragma unroll
            for (int nt = 0; nt < 8; nt++) {
                float2 vb = *(const float2*)&Vc[(nt * 8 + g) * 68 + ks * 8 + 2 * c];
                mma8(o[0][nt], a00, a01, a02, a03, vb.x, vb.y);
                mma8(o[1][nt], a10, a11, a12, a13, vb.x, vb.y);
            }
        }
    }

    #pragma unroll
    for (int i = 0; i < 4; i++) {
        lp[i] += __shfl_xor_sync(~0u, lp[i], 1);
        lp[i] += __shfl_xor_sync(~0u, lp[i], 2);
    }

    #pragma unroll
    for (int mt = 0; mt < 2; mt++) {
        float inv0 = 1.f / lp[2 * mt], inv1 = 1.f / lp[2 * mt + 1];
        int n0 = q0 + w * 32 + mt * 16 + g, n1 = n0 + 8;
        float* ob0 = &g_o[((size_t)(b_ * NTOK + n0)) * 1024 + h * 64];
        float* ob1 = &g_o[((size_t)(b_ * NTOK + n1)) * 1024 + h * 64];
        #pragma unroll
        for (int nt = 0; nt < 8; nt++) {
            int d0 = nt * 8 + 2 * c;
            *(float2*)&ob0[d0] = make_float2(F2TF(o[mt][nt][0] * inv0), F2TF(o[mt][nt][1] * inv0));
            *(float2*)&ob1[d0] = make_float2(F2TF(o[mt][nt][2] * inv1), F2TF(o[mt][nt][3] * inv1));
        }
    }
}

// =============================================================================
// Kernel 3: out = O @ Wo + bo
// =============================================================================
__global__ __launch_bounds__(128) void out_kernel(
    const float* __restrict__ bo, float* __restrict__ out)
{
    extern __shared__ float sm[];
    const int tid = threadIdx.x;
    const int w = tid >> 5, lane = tid & 31, g = lane >> 2, c = lane & 3;
    const int m0 = blockIdx.y * 128;
    const int colb = blockIdx.x * 64;

    float acc[2][8][4] = {};
    gemm_mainloop(g_o, g_wot + (size_t)colb * 1024, sm, tid, w, g, c, m0, acc);

    #pragma unroll
    for (int mt = 0; mt < 2; mt++) {
        int m_a = m0 + w * 32 + mt * 16 + g;
        float* r0 = &out[(size_t)m_a * 1024 + colb];
        float* r1 = &out[(size_t)(m_a + 8) * 1024 + colb];
        #pragma unroll
        for (int nt = 0; nt < 8; nt++) {
            int d0 = nt * 8 + 2 * c;
            float b0v = bo[colb + d0], b1v = bo[colb + d0 + 1];
            *(float2*)&r0[d0] = make_float2(acc[mt][nt][0] + b0v, acc[mt][nt][1] + b1v);
            *(float2*)&r1[d0] = make_float2(acc[mt][nt][2] + b0v, acc[mt][nt][3] + b1v);
        }
    }
}

// =============================================================================
extern "C" void kernel_launch(void* const* d_in, const int* in_sizes, int n_in,
                              void* d_out, int out_size)
{
    const float* x  = (const float*)d_in[0];
    const float* Wq = (const float*)d_in[1];
    const float* bq = (const float*)d_in[2];
    const float* Wk = (const float*)d_in[3];
    const float* bk = (const float*)d_in[4];
    const float* Wv = (const float*)d_in[5];
    const float* bv = (const float*)d_in[6];
    const float* Wo = (const float*)d_in[7];
    const float* bo = (const float*)d_in[8];
    const float* qn = (const float*)d_in[9];
    const float* kn = (const float*)d_in[10];
    float* out = (float*)d_out;

    cudaFuncSetAttribute(qkv_kernel, cudaFuncAttributeMaxDynamicSharedMemorySize, GEMM_SMEM);
    cudaFuncSetAttribute(out_kernel, cudaFuncAttributeMaxDynamicSharedMemorySize, GEMM_SMEM);
    cudaFuncSetAttribute(attn_kernel, cudaFuncAttributeMaxDynamicSharedMemorySize, ATTN_SMEM);

    cvtx_kernel<<<4096, 256>>>((const float4*)x);
    wtr_kernel<<<2560, 256>>>(Wq, Wk, Wv, Wo);
    qkv_kernel<<<dim3(24, 32), 128, GEMM_SMEM>>>(bq, bk, bv, qn, kn);
    attn_kernel<<<dim3(16, 32), 128, ATTN_SMEM>>>();
    out_kernel<<<dim3(16, 32), 128, GEMM_SMEM>>>(bo, out);
}

// round 9
// speedup vs baseline: 1.0636x; 1.0085x over previous
#include <cuda_runtime.h>
#include <math.h>
#include <stdint.h>

#define NTOK 2048

// ---------------- scratch ----------------
__device__ float g_xc [(size_t)4096 * 1024];       // x, tf32  [m][k]
__device__ float g_wqt[(size_t)1024 * 1024];       // Wq^T, tf32  [n][k]
__device__ float g_wkt[(size_t)256  * 1024];       // Wk^T
__device__ float g_wvt[(size_t)256  * 1024];       // Wv^T
__device__ float g_wot[(size_t)1024 * 1024];       // Wo^T
__device__ float g_q [(size_t)2 * 16 * NTOK * 64]; // [b][h][n][d]  tf32, q * (log2e/8)
__device__ float g_k [(size_t)2 * 4  * NTOK * 64]; // [b][kv][n][d] tf32
__device__ float g_vt[(size_t)2 * 4  * 64 * NTOK]; // [b][kv][d][n] tf32 (transposed)
__device__ float g_o [(size_t)4096 * 1024];        // [m][1024]     tf32

__device__ __forceinline__ float F2TF(float x) {
    uint32_t r; asm("cvt.rna.tf32.f32 %0, %1;" : "=r"(r) : "f"(x));
    return __uint_as_float(r);
}
__device__ __forceinline__ float EX2(float x) {
    float y; asm("ex2.approx.f32 %0, %1;" : "=f"(y) : "f"(x));
    return y;
}

__device__ __forceinline__ void mma8(float* d, float a0, float a1, float a2,
                                     float a3, float b0, float b1) {
    asm volatile(
        "mma.sync.aligned.m16n8k8.row.col.f32.tf32.tf32.f32 "
        "{%0,%1,%2,%3},{%4,%5,%6,%7},{%8,%9},{%0,%1,%2,%3};\n"
        : "+f"(d[0]), "+f"(d[1]), "+f"(d[2]), "+f"(d[3])
        : "r"(__float_as_uint(a0)), "r"(__float_as_uint(a1)),
          "r"(__float_as_uint(a2)), "r"(__float_as_uint(a3)),
          "r"(__float_as_uint(b0)), "r"(__float_as_uint(b1)));
}

#define CP_ASYNC16(dst, src) \
    asm volatile("cp.async.cg.shared.global [%0], [%1], 16;\n" :: "r"(dst), "l"(src))
#define CP_COMMIT() asm volatile("cp.async.commit_group;\n" ::: "memory")
#define CP_WAIT0()  asm volatile("cp.async.wait_group 0;\n" ::: "memory")
#define CP_WAIT1()  asm volatile("cp.async.wait_group 1;\n" ::: "memory")

// =============================================================================
// Prep A: x -> tf32 copy
// =============================================================================
__global__ __launch_bounds__(256) void cvtx_kernel(const float4* __restrict__ x)
{
    int i = blockIdx.x * 256 + threadIdx.x;   // 1048576 float4s
    float4 v = x[i];
    ((float4*)g_xc)[i] = make_float4(F2TF(v.x), F2TF(v.y), F2TF(v.z), F2TF(v.w));
}

// =============================================================================
// Prep B: weights -> tf32 + transpose to [n][k]  (32x32 smem tiles)
// =============================================================================
__global__ __launch_bounds__(256) void wtr_kernel(
    const float* __restrict__ wq, const float* __restrict__ wk,
    const float* __restrict__ wv, const float* __restrict__ wo)
{
    __shared__ float ts[32][33];
    int t = blockIdx.x;
    const float* src; float* dst; int N;
    if (t < 1024)      { src = wq; dst = g_wqt; N = 1024; }
    else if (t < 1280) { src = wk; dst = g_wkt; N = 256;  t -= 1024; }
    else if (t < 1536) { src = wv; dst = g_wvt; N = 256;  t -= 1280; }
    else               { src = wo; dst = g_wot; N = 1024; t -= 1536; }
    int tiles_n = N >> 5;
    int k0 = (t / tiles_n) << 5, n0 = (t % tiles_n) << 5;
    int tx = threadIdx.x & 31, ty = threadIdx.x >> 5;
    #pragma unroll
    for (int p = 0; p < 4; p++)
        ts[ty + p * 8][tx] = F2TF(src[(size_t)(k0 + ty + p * 8) * N + n0 + tx]);
    __syncthreads();
    #pragma unroll
    for (int p = 0; p < 4; p++)
        dst[(size_t)(n0 + ty + p * 8) * 1024 + k0 + tx] = ts[tx][ty + p * 8];
}

// =============================================================================
// GEMM mainloop: 128 threads / 4 warps, tile 128x64, k-step 32, 2-stage
// cp.async. A[m][k] pad36; B^T[n][k] pad36 (frags = float2).
// =============================================================================
#define A_SZ (128 * 36)
#define B_SZ (64 * 36)
#define GEMM_SMEM ((2 * A_SZ + 2 * B_SZ) * 4)

__device__ __forceinline__ void gemm_mainloop(
    const float* __restrict__ Amat,
    const float* __restrict__ Bt,
    float* sm, int tid, int w, int g, int c, int m0,
    float acc[2][8][4])
{
    float* As = sm;
    float* Bs = sm + 2 * A_SZ;
    const uint32_t as_u = (uint32_t)__cvta_generic_to_shared(As);
    const uint32_t bs_u = (uint32_t)__cvta_generic_to_shared(Bs);

    const int aRow = tid >> 3, aCol = (tid & 7) * 4;
    const int bRow = tid >> 3, bCol = (tid & 7) * 4;

    {
        #pragma unroll
        for (int p = 0; p < 8; p++)
            CP_ASYNC16(as_u + ((p * 16 + aRow) * 36 + aCol) * 4,
                       &Amat[(size_t)(m0 + p * 16 + aRow) * 1024 + aCol]);
        #pragma unroll
        for (int p = 0; p < 4; p++)
            CP_ASYNC16(bs_u + ((p * 16 + bRow) * 36 + bCol) * 4,
                       &Bt[(size_t)(p * 16 + bRow) * 1024 + bCol]);
        CP_COMMIT();
    }

    for (int i = 0; i < 32; i++) {
        const int cur = i & 1;
        if (i + 1 < 32) {
            const int nxt = 1 - cur;
            const int k0 = (i + 1) * 32;
            #pragma unroll
            for (int p = 0; p < 8; p++)
                CP_ASYNC16(as_u + (nxt * A_SZ + (p * 16 + aRow) * 36 + aCol) * 4,
                           &Amat[(size_t)(m0 + p * 16 + aRow) * 1024 + k0 + aCol]);
            #pragma unroll
            for (int p = 0; p < 4; p++)
                CP_ASYNC16(bs_u + (nxt * B_SZ + (p * 16 + bRow) * 36 + bCol) * 4,
                           &Bt[(size_t)(p * 16 + bRow) * 1024 + k0 + bCol]);
            CP_COMMIT();
            CP_WAIT1();
        } else {
            CP_WAIT0();
        }
        __syncthreads();

        const float* Ac = As + cur * A_SZ;
        const float* Bc = Bs + cur * B_SZ;
        #pragma unroll
        for (int ks = 0; ks < 4; ks++) {
            float2 fa[4];
            #pragma unroll
            for (int r = 0; r < 4; r++)
                fa[r] = *(const float2*)&Ac[(w * 32 + r * 8 + g) * 36 + ks * 8 + 2 * c];
            #pragma unroll
            for (int nt = 0; nt < 8; nt++) {
                float2 wb = *(const float2*)&Bc[(nt * 8 + g) * 36 + ks * 8 + 2 * c];
                mma8(acc[0][nt], fa[0].x, fa[1].x, fa[0].y, fa[1].y, wb.x, wb.y);
                mma8(acc[1][nt], fa[2].x, fa[3].x, fa[2].y, fa[3].y, wb.x, wb.y);
            }
        }
        __syncthreads();
    }
}

// =============================================================================
// Kernel 1: QKV GEMM + bias + RMSNorm + 3D RoPE + q-scale (0.125*log2e)
// =============================================================================
__global__ __launch_bounds__(128) void qkv_kernel(
    const float* __restrict__ bq, const float* __restrict__ bk,
    const float* __restrict__ bv,
    const float* __restrict__ qn, const float* __restrict__ kn)
{
    extern __shared__ float sm[];
    const int tid = threadIdx.x;
    const int w = tid >> 5, lane = tid & 31, g = lane >> 2, c = lane & 3;
    const int m0 = blockIdx.y * 128;
    const int colb = blockIdx.x * 64;

    const float* Bt; const float* bias; int seg, colloc;
    if (colb < 1024)      { Bt = g_wqt; bias = bq; seg = 0; colloc = colb; }
    else if (colb < 1280) { Bt = g_wkt; bias = bk; seg = 1; colloc = colb - 1024; }
    else                  { Bt = g_wvt; bias = bv; seg = 2; colloc = colb - 1280; }

    float acc[2][8][4] = {};
    gemm_mainloop(g_xc, Bt + (size_t)colloc * 1024, sm, tid, w, g, c, m0, acc);

    #pragma unroll
    for (int nt = 0; nt < 8; nt++) {
        float b0v = bias[colloc + nt * 8 + 2 * c];
        float b1v = bias[colloc + nt * 8 + 2 * c + 1];
        #pragma unroll
        for (int mt = 0; mt < 2; mt++) {
            acc[mt][nt][0] += b0v; acc[mt][nt][1] += b1v;
            acc[mt][nt][2] += b0v; acc[mt][nt][3] += b1v;
        }
    }

    const int head = colloc >> 6;

    if (seg == 2) {
        #pragma unroll
        for (int mt = 0; mt < 2; mt++) {
            int m_a = m0 + w * 32 + mt * 16 + g;
            int b_ = m_a >> 11, n0 = m_a & 2047, n1 = n0 + 8;
            float* vb = &g_vt[((size_t)(b_ * 4 + head)) * 64 * NTOK];
            #pragma unroll
            for (int nt = 0; nt < 8; nt++) {
                int d0 = nt * 8 + 2 * c;
                vb[(size_t)d0 * NTOK + n0]       = F2TF(acc[mt][nt][0]);
                vb[(size_t)(d0 + 1) * NTOK + n0] = F2TF(acc[mt][nt][1]);
                vb[(size_t)d0 * NTOK + n1]       = F2TF(acc[mt][nt][2]);
                vb[(size_t)(d0 + 1) * NTOK + n1] = F2TF(acc[mt][nt][3]);
            }
        }
        return;
    }

    // RMSNorm (intra-warp over 64-wide head dim)
    const float* nw = (seg == 0) ? qn : kn;
    #pragma unroll
    for (int mt = 0; mt < 2; mt++) {
        float ss0 = 0.f, ss1 = 0.f;
        #pragma unroll
        for (int nt = 0; nt < 8; nt++) {
            ss0 += acc[mt][nt][0] * acc[mt][nt][0] + acc[mt][nt][1] * acc[mt][nt][1];
            ss1 += acc[mt][nt][2] * acc[mt][nt][2] + acc[mt][nt][3] * acc[mt][nt][3];
        }
        ss0 += __shfl_xor_sync(~0u, ss0, 1); ss0 += __shfl_xor_sync(~0u, ss0, 2);
        ss1 += __shfl_xor_sync(~0u, ss1, 1); ss1 += __shfl_xor_sync(~0u, ss1, 2);
        float rs0 = rsqrtf(ss0 * (1.f / 64.f) + 1e-6f);
        float rs1 = rsqrtf(ss1 * (1.f / 64.f) + 1e-6f);
        #pragma unroll
        for (int nt = 0; nt < 8; nt++) {
            float w0 = nw[nt * 8 + 2 * c], w1 = nw[nt * 8 + 2 * c + 1];
            acc[mt][nt][0] *= rs0 * w0; acc[mt][nt][1] *= rs0 * w1;
            acc[mt][nt][2] *= rs1 * w0; acc[mt][nt][3] *= rs1 * w1;
        }
    }

    // 3D RoPE in-place: pairs t:(0,1) h:(2,3) w:(4,6),(5,7)
    const int lo_[4] = {0, 2, 4, 5};
    const int hi_[4] = {1, 3, 6, 7};
    #pragma unroll
    for (int mt = 0; mt < 2; mt++) {
        int m_a = m0 + w * 32 + mt * 16 + g;
        int n0 = m_a & 2047, n1 = n0 + 8;
        float posr[2][3] = {
            {(float)(n0 >> 8), (float)((n0 >> 4) & 15), (float)(n0 & 15)},
            {(float)(n1 >> 8), (float)((n1 >> 4) & 15), (float)(n1 & 15)}};
        #pragma unroll
        for (int pi = 0; pi < 4; pi++) {
            int lo = lo_[pi], hi = hi_[pi];
            int ax = (pi == 0) ? 0 : (pi == 1 ? 1 : 2);
            float halfinv = (pi < 2) ? (1.f / 8.f) : (1.f / 16.f);
            #pragma unroll
            for (int e = 0; e < 2; e++) {
                float f = (pi < 2) ? (float)(2 * c + e)
                                   : (float)((lo & 1) * 8 + 2 * c + e);
                float inv = __powf(10000.f, -f * halfinv);
                #pragma unroll
                for (int r = 0; r < 2; r++) {
                    float sv, cv;
                    __sincosf(posr[r][ax] * inv, &sv, &cv);
                    float xl = acc[mt][lo][2 * r + e];
                    float xh = acc[mt][hi][2 * r + e];
                    acc[mt][lo][2 * r + e] = xl * cv - xh * sv;
                    acc[mt][hi][2 * r + e] = xh * cv + xl * sv;
                }
            }
        }
    }

    // q scale folds HD^-0.5 AND log2(e) (softmax exp via ex2)
    float scale = (seg == 0) ? (0.125f * 1.4426950408889634f) : 1.f;
    #pragma unroll
    for (int mt = 0; mt < 2; mt++) {
        int m_a = m0 + w * 32 + mt * 16 + g;
        int b_ = m_a >> 11, n0 = m_a & 2047, n1 = n0 + 8;
        float* qb = (seg == 0) ? &g_q[((size_t)(b_ * 16 + head)) * NTOK * 64]
                               : &g_k[((size_t)(b_ * 4 + head)) * NTOK * 64];
        #pragma unroll
        for (int nt = 0; nt < 8; nt++) {
            int d0 = nt * 8 + 2 * c;
            *(float2*)&qb[(size_t)n0 * 64 + d0] =
                make_float2(F2TF(acc[mt][nt][0] * scale), F2TF(acc[mt][nt][1] * scale));
            *(float2*)&qb[(size_t)n1 * 64 + d0] =
                make_float2(F2TF(acc[mt][nt][2] * scale), F2TF(acc[mt][nt][3] * scale));
        }
    }
}

// =============================================================================
// Kernel 2: flash attention. 128 threads / 4 warps, warp M=32, q-block 128.
//   K+V double-buffered, one wait+sync per tile. No online max; ex2 softmax.
//   __launch_bounds__(128,3): cap regs at ~170 -> 3 blocks/SM, 1.15 waves.
//   P fed to PV mma WITHOUT cvt (HMMA reads tf32 field; HW truncation).
// =============================================================================
#define KV_TILE (64 * 68)
#define ATTN_SMEM (4 * KV_TILE * 4)   // 2 bufs x (K + V)

__global__ __launch_bounds__(128, 3) void attn_kernel()
{
    extern __shared__ float sm[];     // [buf][ K(4352) | V(4352) ]

    const int tid = threadIdx.x;
    const int w = tid >> 5, lane = tid & 31, g = lane >> 2, c = lane & 3;
    const int q0 = blockIdx.x * 128;
    const int bh = blockIdx.y;
    const int b_ = bh >> 4, h = bh & 15, kv = h >> 2;

    const float* qg = &g_q[((size_t)(b_ * 16 + h)) * NTOK * 64];
    const float* kg = &g_k[((size_t)(b_ * 4 + kv)) * NTOK * 64];
    const float* vg = &g_vt[((size_t)(b_ * 4 + kv)) * 64 * NTOK];

    const int lr = tid >> 1, lc = (tid & 1) * 32;
    const uint32_t k_u = (uint32_t)__cvta_generic_to_shared(sm) + (lr * 68 + lc) * 4;
    const uint32_t v_u = k_u + KV_TILE * 4;

    // Q fragments register-resident: rows w*32+g {+0,+8} (mt0), {+16,+24} (mt1)
    float qf[2][8][4];
    {
        const float* r0 = &qg[(size_t)(q0 + w * 32 + g) * 64];
        #pragma unroll
        for (int ks = 0; ks < 8; ks++) {
            float2 a = *(const float2*)&r0[ks * 8 + 2 * c];
            float2 b = *(const float2*)&r0[8 * 64 + ks * 8 + 2 * c];
            float2 d = *(const float2*)&r0[16 * 64 + ks * 8 + 2 * c];
            float2 e = *(const float2*)&r0[24 * 64 + ks * 8 + 2 * c];
            qf[0][ks][0] = a.x; qf[0][ks][1] = b.x; qf[0][ks][2] = a.y; qf[0][ks][3] = b.y;
            qf[1][ks][0] = d.x; qf[1][ks][1] = e.x; qf[1][ks][2] = d.y; qf[1][ks][3] = e.y;
        }
    }

    float o[2][8][4] = {};
    float lp[4] = {0.f, 0.f, 0.f, 0.f};

    // prologue: K0 + V0
    #pragma unroll
    for (int i = 0; i < 8; i++) {
        CP_ASYNC16(k_u + i * 16, &kg[(size_t)lr * 64 + lc + i * 4]);
        CP_ASYNC16(v_u + i * 16, &vg[(size_t)lr * NTOK + lc + i * 4]);
    }
    CP_COMMIT();

    for (int kt = 0; kt < NTOK; kt += 64) {
        const int buf = (kt >> 6) & 1;
        CP_WAIT0();
        __syncthreads();   // tile(t) resident; all warps done with tile(t-1)

        if (kt + 64 < NTOK) {   // load tile(t+1) into other buffer, under compute
            const uint32_t off = (1 - buf) * 2 * KV_TILE * 4;
            #pragma unroll
            for (int i = 0; i < 8; i++) {
                CP_ASYNC16(k_u + off + i * 16, &kg[(size_t)(kt + 64 + lr) * 64 + lc + i * 4]);
                CP_ASYNC16(v_u + off + i * 16, &vg[(size_t)lr * NTOK + kt + 64 + lc + i * 4]);
            }
            CP_COMMIT();
        }

        const float* Kc = sm + buf * 2 * KV_TILE;
        const float* Vc = Kc + KV_TILE;

        // S = Q K^T  (each K frag feeds both mt halves)
        float s[2][8][4] = {};
        #pragma unroll
        for (int ks = 0; ks < 8; ks++) {
            #pragma unroll
            for (int nt = 0; nt < 8; nt++) {
                float2 kb = *(const float2*)&Kc[(nt * 8 + g) * 68 + ks * 8 + 2 * c];
                mma8(s[0][nt], qf[0][ks][0], qf[0][ks][1], qf[0][ks][2], qf[0][ks][3], kb.x, kb.y);
                mma8(s[1][nt], qf[1][ks][0], qf[1][ks][1], qf[1][ks][2], qf[1][ks][3], kb.x, kb.y);
            }
        }

        // p = 2^s (bounded; no max shift) + partial row sums
        #pragma unroll
        for (int mt = 0; mt < 2; mt++)
            #pragma unroll
            for (int nt = 0; nt < 8; nt++) {
                s[mt][nt][0] = EX2(s[mt][nt][0]); s[mt][nt][1] = EX2(s[mt][nt][1]);
                s[mt][nt][2] = EX2(s[mt][nt][2]); s[mt][nt][3] = EX2(s[mt][nt][3]);
                lp[2 * mt]     += s[mt][nt][0] + s[mt][nt][1];
                lp[2 * mt + 1] += s[mt][nt][2] + s[mt][nt][3];
            }

        // O += P V  (P fed raw: HMMA truncates fp32->tf32 in HW)
        #pragma unroll
        for (int ks = 0; ks < 8; ks++) {
            #pragma unroll
            for (int nt = 0; nt < 8; nt++) {
                float2 vb = *(const float2*)&Vc[(nt * 8 + g) * 68 + ks * 8 + 2 * c];
                mma8(o[0][nt], s[0][ks][0], s[0][ks][2], s[0][ks][1], s[0][ks][3], vb.x, vb.y);
                mma8(o[1][nt], s[1][ks][0], s[1][ks][2], s[1][ks][1], s[1][ks][3], vb.x, vb.y);
            }
        }
    }

    #pragma unroll
    for (int i = 0; i < 4; i++) {
        lp[i] += __shfl_xor_sync(~0u, lp[i], 1);
        lp[i] += __shfl_xor_sync(~0u, lp[i], 2);
    }

    #pragma unroll
    for (int mt = 0; mt < 2; mt++) {
        float inv0 = 1.f / lp[2 * mt], inv1 = 1.f / lp[2 * mt + 1];
        int n0 = q0 + w * 32 + mt * 16 + g, n1 = n0 + 8;
        float* ob0 = &g_o[((size_t)(b_ * NTOK + n0)) * 1024 + h * 64];
        float* ob1 = &g_o[((size_t)(b_ * NTOK + n1)) * 1024 + h * 64];
        #pragma unroll
        for (int nt = 0; nt < 8; nt++) {
            int d0 = nt * 8 + 2 * c;
            *(float2*)&ob0[d0] = make_float2(F2TF(o[mt][nt][0] * inv0), F2TF(o[mt][nt][1] * inv0));
            *(float2*)&ob1[d0] = make_float2(F2TF(o[mt][nt][2] * inv1), F2TF(o[mt][nt][3] * inv1));
        }
    }
}

// =============================================================================
// Kernel 3: out = O @ Wo + bo
// =============================================================================
__global__ __launch_bounds__(128) void out_kernel(
    const float* __restrict__ bo, float* __restrict__ out)
{
    extern __shared__ float sm[];
    const int tid = threadIdx.x;
    const int w = tid >> 5, lane = tid & 31, g = lane >> 2, c = lane & 3;
    const int m0 = blockIdx.y * 128;
    const int colb = blockIdx.x * 64;

    float acc[2][8][4] = {};
    gemm_mainloop(g_o, g_wot + (size_t)colb * 1024, sm, tid, w, g, c, m0, acc);

    #pragma unroll
    for (int mt = 0; mt < 2; mt++) {
        int m_a = m0 + w * 32 + mt * 16 + g;
        float* r0 = &out[(size_t)m_a * 1024 + colb];
        float* r1 = &out[(size_t)(m_a + 8) * 1024 + colb];
        #pragma unroll
        for (int nt = 0; nt < 8; nt++) {
            int d0 = nt * 8 + 2 * c;
            float b0v = bo[colb + d0], b1v = bo[colb + d0 + 1];
            *(float2*)&r0[d0] = make_float2(acc[mt][nt][0] + b0v, acc[mt][nt][1] + b1v);
            *(float2*)&r1[d0] = make_float2(acc[mt][nt][2] + b0v, acc[mt][nt][3] + b1v);
        }
    }
}

// =============================================================================
extern "C" void kernel_launch(void* const* d_in, const int* in_sizes, int n_in,
                              void* d_out, int out_size)
{
    const float* x  = (const float*)d_in[0];
    const float* Wq = (const float*)d_in[1];
    const float* bq = (const float*)d_in[2];
    const float* Wk = (const float*)d_in[3];
    const float* bk = (const float*)d_in[4];
    const float* Wv = (const float*)d_in[5];
    const float* bv = (const float*)d_in[6];
    const float* Wo = (const float*)d_in[7];
    const float* bo = (const float*)d_in[8];
    const float* qn = (const float*)d_in[9];
    const float* kn = (const float*)d_in[10];
    float* out = (float*)d_out;

    cudaFuncSetAttribute(qkv_kernel, cudaFuncAttributeMaxDynamicSharedMemorySize, GEMM_SMEM);
    cudaFuncSetAttribute(out_kernel, cudaFuncAttributeMaxDynamicSharedMemorySize, GEMM_SMEM);
    cudaFuncSetAttribute(attn_kernel, cudaFuncAttributeMaxDynamicSharedMemorySize, ATTN_SMEM);

    cvtx_kernel<<<4096, 256>>>((const float4*)x);
    wtr_kernel<<<2560, 256>>>(Wq, Wk, Wv, Wo);
    qkv_kernel<<<dim3(24, 32), 128, GEMM_SMEM>>>(bq, bk, bv, qn, kn);
    attn_kernel<<<dim3(16, 32), 128, ATTN_SMEM>>>();
    out_kernel<<<dim3(16, 32), 128, GEMM_SMEM>>>(bo, out);
}

// round 11
// speedup vs baseline: 2.3751x; 2.2331x over previous
#include <cuda_runtime.h>
#include <cuda_fp16.h>
#include <math.h>
#include <stdint.h>

#define NTOK 2048

// ---------------- scratch (fp16 operands) ----------------
__device__ __half g_xh [(size_t)4096 * 1024];       // x       [m][k]
__device__ __half g_wqt[(size_t)1024 * 1024];       // Wq^T    [n][k]
__device__ __half g_wkt[(size_t)256  * 1024];
__device__ __half g_wvt[(size_t)256  * 1024];
__device__ __half g_wot[(size_t)1024 * 1024];
__device__ __half g_q [(size_t)2 * 16 * NTOK * 64]; // [b][h][n][d], q*(log2e/8)
__device__ __half g_k [(size_t)2 * 4  * NTOK * 64];
__device__ __half g_vt[(size_t)2 * 4  * 64 * NTOK]; // [b][kv][d][n]
__device__ __half g_o [(size_t)4096 * 1024];

__device__ __forceinline__ float EX2(float x) {
    float y; asm("ex2.approx.f32 %0, %1;" : "=f"(y) : "f"(x));
    return y;
}
__device__ __forceinline__ uint32_t PK2(float a, float b) {
    __half2 h = __floats2half2_rn(a, b);
    return *(uint32_t*)&h;
}
__device__ __forceinline__ uint32_t smem_u32(const void* p) {
    uint32_t a;
    asm("{ .reg .u64 t; cvta.to.shared.u64 t, %1; cvt.u32.u64 %0, t; }"
        : "=r"(a) : "l"(p));
    return a;
}

// D(16x8,f32) += A(16x16,f16) * B(16x8,f16)
__device__ __forceinline__ void mma16(float* d, uint32_t a0, uint32_t a1,
                                      uint32_t a2, uint32_t a3,
                                      uint32_t b0, uint32_t b1) {
    asm volatile(
        "mma.sync.aligned.m16n8k16.row.col.f32.f16.f16.f32 "
        "{%0,%1,%2,%3},{%4,%5,%6,%7},{%8,%9},{%0,%1,%2,%3};\n"
        : "+f"(d[0]), "+f"(d[1]), "+f"(d[2]), "+f"(d[3])
        : "r"(a0), "r"(a1), "r"(a2), "r"(a3), "r"(b0), "r"(b1));
}

#define LDSM4(r0, r1, r2, r3, addr) \
    asm volatile("ldmatrix.sync.aligned.m8n8.x4.shared.b16 {%0,%1,%2,%3}, [%4];" \
                 : "=r"(r0), "=r"(r1), "=r"(r2), "=r"(r3) : "r"(addr))

#define CP_ASYNC16(dst, src) \
    asm volatile("cp.async.cg.shared.global [%0], [%1], 16;\n" :: "r"(dst), "l"(src))
#define CP_COMMIT() asm volatile("cp.async.commit_group;\n" ::: "memory")
#define CP_WAIT0()  asm volatile("cp.async.wait_group 0;\n" ::: "memory")
#define CP_WAIT1()  asm volatile("cp.async.wait_group 1;\n" ::: "memory")

// =============================================================================
// Prep A: x -> fp16
// =============================================================================
__global__ __launch_bounds__(256) void cvtx_kernel(const float4* __restrict__ x)
{
    int i = blockIdx.x * 256 + threadIdx.x;   // 1048576 float4
    float4 v = x[i];
    uint2 o;
    o.x = PK2(v.x, v.y);
    o.y = PK2(v.z, v.w);
    ((uint2*)g_xh)[i] = o;
}

// =============================================================================
// Prep B: weights -> fp16 + transpose to [n][k]
// =============================================================================
__global__ __launch_bounds__(256) void wtr_kernel(
    const float* __restrict__ wq, const float* __restrict__ wk,
    const float* __restrict__ wv, const float* __restrict__ wo)
{
    __shared__ float ts[32][33];
    int t = blockIdx.x;
    const float* src; __half* dst; int N;
    if (t < 1024)      { src = wq; dst = g_wqt; N = 1024; }
    else if (t < 1280) { src = wk; dst = g_wkt; N = 256;  t -= 1024; }
    else if (t < 1536) { src = wv; dst = g_wvt; N = 256;  t -= 1280; }
    else               { src = wo; dst = g_wot; N = 1024; t -= 1536; }
    int tiles_n = N >> 5;
    int k0 = (t / tiles_n) << 5, n0 = (t % tiles_n) << 5;
    int tx = threadIdx.x & 31, ty = threadIdx.x >> 5;
    #pragma unroll
    for (int p = 0; p < 4; p++)
        ts[ty + p * 8][tx] = src[(size_t)(k0 + ty + p * 8) * N + n0 + tx];
    __syncthreads();
    #pragma unroll
    for (int p = 0; p < 4; p++)
        dst[(size_t)(n0 + ty + p * 8) * 1024 + k0 + tx] = __float2half(ts[tx][ty + p * 8]);
}

// =============================================================================
// fp16 GEMM mainloop: 128 thr / 4 warps, tile 128x64, k-step 32 (2 k16 chunks),
// 2-stage cp.async. A[m][k] pad40h (80B), B^T[n][k] pad40h. ldmatrix frags.
// =============================================================================
#define APAD 40
#define A_SZ (128 * APAD)   // halfs
#define B_SZ (64 * APAD)

__device__ __forceinline__ void gemm_fp16(
    const __half* __restrict__ A, const __half* __restrict__ Bt,
    __half* sa, __half* sb, int tid, int w, int lane, float acc[2][8][4])
{
    const uint32_t as_u = smem_u32(sa);
    const uint32_t bs_u = smem_u32(sb);
    const int ldr = tid >> 2, ldc = tid & 3;       // 32 rows/pass, 16B chunks

    // ldmatrix per-lane offsets (bytes)
    const int m_ = lane >> 3, r_ = lane & 7;
    const uint32_t a_off = ((m_ & 1) * 8 + r_) * (APAD * 2) + (m_ >> 1) * 16;
    const uint32_t b_off = ((m_ >> 1) * 8 + r_) * (APAD * 2) + (m_ & 1) * 16;

    // prologue: stage 0
    #pragma unroll
    for (int p = 0; p < 4; p++)
        CP_ASYNC16(as_u + ((p * 32 + ldr) * APAD) * 2 + ldc * 16,
                   &A[(size_t)(p * 32 + ldr) * 1024 + ldc * 8]);
    #pragma unroll
    for (int p = 0; p < 2; p++)
        CP_ASYNC16(bs_u + ((p * 32 + ldr) * APAD) * 2 + ldc * 16,
                   &Bt[(size_t)(p * 32 + ldr) * 1024 + ldc * 8]);
    CP_COMMIT();

    for (int i = 0; i < 32; i++) {
        const int cur = i & 1;
        if (i + 1 < 32) {
            const int nxt = 1 - cur;
            const int k0 = (i + 1) * 32;
            #pragma unroll
            for (int p = 0; p < 4; p++)
                CP_ASYNC16(as_u + (nxt * A_SZ + (p * 32 + ldr) * APAD) * 2 + ldc * 16,
                           &A[(size_t)(p * 32 + ldr) * 1024 + k0 + ldc * 8]);
            #pragma unroll
            for (int p = 0; p < 2; p++)
                CP_ASYNC16(bs_u + (nxt * B_SZ + (p * 32 + ldr) * APAD) * 2 + ldc * 16,
                           &Bt[(size_t)(p * 32 + ldr) * 1024 + k0 + ldc * 8]);
            CP_COMMIT();
            CP_WAIT1();
        } else {
            CP_WAIT0();
        }
        __syncthreads();

        const uint32_t ab = as_u + cur * A_SZ * 2;
        const uint32_t bb = bs_u + cur * B_SZ * 2;
        #pragma unroll
        for (int ks = 0; ks < 2; ks++) {
            uint32_t af[2][4];
            #pragma unroll
            for (int mt = 0; mt < 2; mt++)
                LDSM4(af[mt][0], af[mt][1], af[mt][2], af[mt][3],
                      ab + (w * 32 + mt * 16) * (APAD * 2) + ks * 32 + a_off);
            #pragma unroll
            for (int p = 0; p < 4; p++) {
                uint32_t b0a, b1a, b0b, b1b;
                LDSM4(b0a, b1a, b0b, b1b,
                      bb + (p * 16) * (APAD * 2) + ks * 32 + b_off);
                #pragma unroll
                for (int mt = 0; mt < 2; mt++) {
                    mma16(acc[mt][2 * p],     af[mt][0], af[mt][1], af[mt][2], af[mt][3], b0a, b1a);
                    mma16(acc[mt][2 * p + 1], af[mt][0], af[mt][1], af[mt][2], af[mt][3], b0b, b1b);
                }
            }
        }
        __syncthreads();
    }
}

// =============================================================================
// Kernel 1: QKV GEMM + bias + RMSNorm + 3D RoPE + q-scale (0.125*log2e)
// =============================================================================
__global__ __launch_bounds__(128) void qkv_kernel(
    const float* __restrict__ bq, const float* __restrict__ bk,
    const float* __restrict__ bv,
    const float* __restrict__ qn, const float* __restrict__ kn)
{
    __shared__ __half sa[2 * A_SZ];
    __shared__ __half sb[2 * B_SZ];
    const int tid = threadIdx.x;
    const int w = tid >> 5, lane = tid & 31, g = lane >> 2, c = lane & 3;
    const int m0 = blockIdx.y * 128;
    const int colb = blockIdx.x * 64;

    const __half* Bt; const float* bias; int seg, colloc;
    if (colb < 1024)      { Bt = g_wqt; bias = bq; seg = 0; colloc = colb; }
    else if (colb < 1280) { Bt = g_wkt; bias = bk; seg = 1; colloc = colb - 1024; }
    else                  { Bt = g_wvt; bias = bv; seg = 2; colloc = colb - 1280; }

    float acc[2][8][4] = {};
    gemm_fp16(g_xh + (size_t)m0 * 1024, Bt + (size_t)colloc * 1024,
              sa, sb, tid, w, lane, acc);

    #pragma unroll
    for (int nt = 0; nt < 8; nt++) {
        float b0v = bias[colloc + nt * 8 + 2 * c];
        float b1v = bias[colloc + nt * 8 + 2 * c + 1];
        #pragma unroll
        for (int mt = 0; mt < 2; mt++) {
            acc[mt][nt][0] += b0v; acc[mt][nt][1] += b1v;
            acc[mt][nt][2] += b0v; acc[mt][nt][3] += b1v;
        }
    }

    const int head = colloc >> 6;

    if (seg == 2) {
        #pragma unroll
        for (int mt = 0; mt < 2; mt++) {
            int m_a = m0 + w * 32 + mt * 16 + g;
            int b_ = m_a >> 11, n0 = m_a & 2047, n1 = n0 + 8;
            __half* vb = &g_vt[((size_t)(b_ * 4 + head)) * 64 * NTOK];
            #pragma unroll
            for (int nt = 0; nt < 8; nt++) {
                int d0 = nt * 8 + 2 * c;
                vb[(size_t)d0 * NTOK + n0]       = __float2half(acc[mt][nt][0]);
                vb[(size_t)(d0 + 1) * NTOK + n0] = __float2half(acc[mt][nt][1]);
                vb[(size_t)d0 * NTOK + n1]       = __float2half(acc[mt][nt][2]);
                vb[(size_t)(d0 + 1) * NTOK + n1] = __float2half(acc[mt][nt][3]);
            }
        }
        return;
    }

    // RMSNorm (intra-warp over 64-wide head dim)
    const float* nw = (seg == 0) ? qn : kn;
    #pragma unroll
    for (int mt = 0; mt < 2; mt++) {
        float ss0 = 0.f, ss1 = 0.f;
        #pragma unroll
        for (int nt = 0; nt < 8; nt++) {
            ss0 += acc[mt][nt][0] * acc[mt][nt][0] + acc[mt][nt][1] * acc[mt][nt][1];
            ss1 += acc[mt][nt][2] * acc[mt][nt][2] + acc[mt][nt][3] * acc[mt][nt][3];
        }
        ss0 += __shfl_xor_sync(~0u, ss0, 1); ss0 += __shfl_xor_sync(~0u, ss0, 2);
        ss1 += __shfl_xor_sync(~0u, ss1, 1); ss1 += __shfl_xor_sync(~0u, ss1, 2);
        float rs0 = rsqrtf(ss0 * (1.f / 64.f) + 1e-6f);
        float rs1 = rsqrtf(ss1 * (1.f / 64.f) + 1e-6f);
        #pragma unroll
        for (int nt = 0; nt < 8; nt++) {
            float w0 = nw[nt * 8 + 2 * c], w1 = nw[nt * 8 + 2 * c + 1];
            acc[mt][nt][0] *= rs0 * w0; acc[mt][nt][1] *= rs0 * w1;
            acc[mt][nt][2] *= rs1 * w0; acc[mt][nt][3] *= rs1 * w1;
        }
    }

    // 3D RoPE in-place: pairs t:(0,1) h:(2,3) w:(4,6),(5,7)
    const int lo_[4] = {0, 2, 4, 5};
    const int hi_[4] = {1, 3, 6, 7};
    #pragma unroll
    for (int mt = 0; mt < 2; mt++) {
        int m_a = m0 + w * 32 + mt * 16 + g;
        int n0 = m_a & 2047, n1 = n0 + 8;
        float posr[2][3] = {
            {(float)(n0 >> 8), (float)((n0 >> 4) & 15), (float)(n0 & 15)},
            {(float)(n1 >> 8), (float)((n1 >> 4) & 15), (float)(n1 & 15)}};
        #pragma unroll
        for (int pi = 0; pi < 4; pi++) {
            int lo = lo_[pi], hi = hi_[pi];
            int ax = (pi == 0) ? 0 : (pi == 1 ? 1 : 2);
            float halfinv = (pi < 2) ? (1.f / 8.f) : (1.f / 16.f);
            #pragma unroll
            for (int e = 0; e < 2; e++) {
                float f = (pi < 2) ? (float)(2 * c + e)
                                   : (float)((lo & 1) * 8 + 2 * c + e);
                float inv = __powf(10000.f, -f * halfinv);
                #pragma unroll
                for (int r = 0; r < 2; r++) {
                    float sv, cv;
                    __sincosf(posr[r][ax] * inv, &sv, &cv);
                    float xl = acc[mt][lo][2 * r + e];
                    float xh = acc[mt][hi][2 * r + e];
                    acc[mt][lo][2 * r + e] = xl * cv - xh * sv;
                    acc[mt][hi][2 * r + e] = xh * cv + xl * sv;
                }
            }
        }
    }

    float sc = (seg == 0) ? (0.125f * 1.4426950408889634f) : 1.f;
    #pragma unroll
    for (int mt = 0; mt < 2; mt++) {
        int m_a = m0 + w * 32 + mt * 16 + g;
        int b_ = m_a >> 11, n0 = m_a & 2047, n1 = n0 + 8;
        __half* qb = (seg == 0) ? &g_q[((size_t)(b_ * 16 + head)) * NTOK * 64]
                                : &g_k[((size_t)(b_ * 4 + head)) * NTOK * 64];
        #pragma unroll
        for (int nt = 0; nt < 8; nt++) {
            int d0 = nt * 8 + 2 * c;
            *(uint32_t*)&qb[(size_t)n0 * 64 + d0] = PK2(acc[mt][nt][0] * sc, acc[mt][nt][1] * sc);
            *(uint32_t*)&qb[(size_t)n1 * 64 + d0] = PK2(acc[mt][nt][2] * sc, acc[mt][nt][3] * sc);
        }
    }
}

// =============================================================================
// Kernel 2: flash attention fp16. 128 thr / 4 warps, warp M=32, q-block 128.
//   K+V double-buffered cp.async; ldmatrix.x4 frags; no online max; ex2.
//   Ks [key][d] pad 72h (144B); Vs [d][key] pad 72h.
// =============================================================================
#define KVP 72

__global__ __launch_bounds__(128) void attn_kernel()
{
    __shared__ __half kvs[2][2][64 * KVP];   // [buf][K/V][...]

    const int tid = threadIdx.x;
    const int w = tid >> 5, lane = tid & 31, g = lane >> 2, c = lane & 3;
    const int q0 = blockIdx.x * 128;
    const int bh = blockIdx.y;
    const int b_ = bh >> 4, h = bh & 15, kv = h >> 2;

    const __half* qg = &g_q[((size_t)(b_ * 16 + h)) * NTOK * 64];
    const __half* kg = &g_k[((size_t)(b_ * 4 + kv)) * NTOK * 64];
    const __half* vg = &g_vt[((size_t)(b_ * 4 + kv)) * 64 * NTOK];

    const int lr = tid >> 1, lc = tid & 1;   // 64 rows x 2 half-rows(64B)
    const uint32_t k_u = smem_u32(&kvs[0][0][0]) + lr * (KVP * 2) + lc * 64;
    const uint32_t v_u = smem_u32(&kvs[0][1][0]) + lr * (KVP * 2) + lc * 64;
    const uint32_t bufstride = 2 * 64 * KVP * 2;   // bytes between buffers

    // ldmatrix per-lane B-frag offset
    const int m_ = lane >> 3, r_ = lane & 7;
    const uint32_t b_off = ((m_ >> 1) * 8 + r_) * (KVP * 2) + (m_ & 1) * 16;
    const uint32_t kbase = smem_u32(&kvs[0][0][0]) + b_off;
    const uint32_t vbase = smem_u32(&kvs[0][1][0]) + b_off;

    // Q fragments register-resident (canonical m16n8k16 A layout)
    uint32_t qf[2][4][4];
    {
        const __half* r0 = &qg[(size_t)(q0 + w * 32 + g) * 64];
        #pragma unroll
        for (int mt = 0; mt < 2; mt++)
            #pragma unroll
            for (int kc = 0; kc < 4; kc++) {
                qf[mt][kc][0] = *(const uint32_t*)&r0[mt * 16 * 64 + kc * 16 + 2 * c];
                qf[mt][kc][1] = *(const uint32_t*)&r0[(mt * 16 + 8) * 64 + kc * 16 + 2 * c];
                qf[mt][kc][2] = *(const uint32_t*)&r0[mt * 16 * 64 + kc * 16 + 8 + 2 * c];
                qf[mt][kc][3] = *(const uint32_t*)&r0[(mt * 16 + 8) * 64 + kc * 16 + 8 + 2 * c];
            }
    }

    float o[2][8][4] = {};
    float lp[4] = {0.f, 0.f, 0.f, 0.f};

    // prologue: K0 + V0
    #pragma unroll
    for (int i = 0; i < 4; i++) {
        CP_ASYNC16(k_u + i * 16, &kg[(size_t)lr * 64 + lc * 32 + i * 8]);
        CP_ASYNC16(v_u + i * 16, &vg[(size_t)lr * NTOK + lc * 32 + i * 8]);
    }
    CP_COMMIT();

    for (int kt = 0; kt < NTOK; kt += 64) {
        const int buf = (kt >> 6) & 1;
        CP_WAIT0();
        __syncthreads();

        if (kt + 64 < NTOK) {
            const uint32_t off = (1 - buf) * bufstride;
            #pragma unroll
            for (int i = 0; i < 4; i++) {
                CP_ASYNC16(k_u + off + i * 16, &kg[(size_t)(kt + 64 + lr) * 64 + lc * 32 + i * 8]);
                CP_ASYNC16(v_u + off + i * 16, &vg[(size_t)lr * NTOK + kt + 64 + lc * 32 + i * 8]);
            }
            CP_COMMIT();
        }

        const uint32_t kb = kbase + buf * bufstride;
        const uint32_t vb = vbase + buf * bufstride;

        // S = Q K^T
        float s[2][8][4] = {};
        #pragma unroll
        for (int kc = 0; kc < 4; kc++) {
            #pragma unroll
            for (int p = 0; p < 4; p++) {
                uint32_t b0a, b1a, b0b, b1b;
                LDSM4(b0a, b1a, b0b, b1b, kb + p * 16 * (KVP * 2) + kc * 32);
                #pragma unroll
                for (int mt = 0; mt < 2; mt++) {
                    mma16(s[mt][2 * p],     qf[mt][kc][0], qf[mt][kc][1], qf[mt][kc][2], qf[mt][kc][3], b0a, b1a);
                    mma16(s[mt][2 * p + 1], qf[mt][kc][0], qf[mt][kc][1], qf[mt][kc][2], qf[mt][kc][3], b0b, b1b);
                }
            }
        }

        // p = 2^s (bounded; no max shift) + partial row sums
        #pragma unroll
        for (int mt = 0; mt < 2; mt++)
            #pragma unroll
            for (int nt = 0; nt < 8; nt++) {
                s[mt][nt][0] = EX2(s[mt][nt][0]); s[mt][nt][1] = EX2(s[mt][nt][1]);
                s[mt][nt][2] = EX2(s[mt][nt][2]); s[mt][nt][3] = EX2(s[mt][nt][3]);
                lp[2 * mt]     += s[mt][nt][0] + s[mt][nt][1];
                lp[2 * mt + 1] += s[mt][nt][2] + s[mt][nt][3];
            }

        // O += P V  (pack P C-frag -> fp16 A-frag; keys 16 per chunk = 2 s-tiles)
        #pragma unroll
        for (int kc = 0; kc < 4; kc++) {
            uint32_t pa[2][4];
            #pragma unroll
            for (int mt = 0; mt < 2; mt++) {
                pa[mt][0] = PK2(s[mt][2 * kc][0],     s[mt][2 * kc][1]);
                pa[mt][1] = PK2(s[mt][2 * kc][2],     s[mt][2 * kc][3]);
                pa[mt][2] = PK2(s[mt][2 * kc + 1][0], s[mt][2 * kc + 1][1]);
                pa[mt][3] = PK2(s[mt][2 * kc + 1][2], s[mt][2 * kc + 1][3]);
            }
            #pragma unroll
            for (int p = 0; p < 4; p++) {
                uint32_t b0a, b1a, b0b, b1b;
                LDSM4(b0a, b1a, b0b, b1b, vb + p * 16 * (KVP * 2) + kc * 32);
                #pragma unroll
                for (int mt = 0; mt < 2; mt++) {
                    mma16(o[mt][2 * p],     pa[mt][0], pa[mt][1], pa[mt][2], pa[mt][3], b0a, b1a);
                    mma16(o[mt][2 * p + 1], pa[mt][0], pa[mt][1], pa[mt][2], pa[mt][3], b0b, b1b);
                }
            }
        }
    }

    #pragma unroll
    for (int i = 0; i < 4; i++) {
        lp[i] += __shfl_xor_sync(~0u, lp[i], 1);
        lp[i] += __shfl_xor_sync(~0u, lp[i], 2);
    }

    #pragma unroll
    for (int mt = 0; mt < 2; mt++) {
        float inv0 = 1.f / lp[2 * mt], inv1 = 1.f / lp[2 * mt + 1];
        int n0 = q0 + w * 32 + mt * 16 + g, n1 = n0 + 8;
        __half* ob0 = &g_o[((size_t)(b_ * NTOK + n0)) * 1024 + h * 64];
        __half* ob1 = &g_o[((size_t)(b_ * NTOK + n1)) * 1024 + h * 64];
        #pragma unroll
        for (int nt = 0; nt < 8; nt++) {
            int d0 = nt * 8 + 2 * c;
            *(uint32_t*)&ob0[d0] = PK2(o[mt][nt][0] * inv0, o[mt][nt][1] * inv0);
            *(uint32_t*)&ob1[d0] = PK2(o[mt][nt][2] * inv1, o[mt][nt][3] * inv1);
        }
    }
}

// =============================================================================
// Kernel 3: out = O @ Wo + bo  (fp16 operands, fp32 out)
// =============================================================================
__global__ __launch_bounds__(128) void out_kernel(
    const float* __restrict__ bo, float* __restrict__ out)
{
    __shared__ __half sa[2 * A_SZ];
    __shared__ __half sb[2 * B_SZ];
    const int tid = threadIdx.x;
    const int w = tid >> 5, lane = tid & 31, g = lane >> 2, c = lane & 3;
    const int m0 = blockIdx.y * 128;
    const int colb = blockIdx.x * 64;

    float acc[2][8][4] = {};
    gemm_fp16(g_o + (size_t)m0 * 1024, g_wot + (size_t)colb * 1024,
              sa, sb, tid, w, lane, acc);

    #pragma unroll
    for (int mt = 0; mt < 2; mt++) {
        int m_a = m0 + w * 32 + mt * 16 + g;
        float* r0 = &out[(size_t)m_a * 1024 + colb];
        float* r1 = &out[(size_t)(m_a + 8) * 1024 + colb];
        #pragma unroll
        for (int nt = 0; nt < 8; nt++) {
            int d0 = nt * 8 + 2 * c;
            float b0v = bo[colb + d0], b1v = bo[colb + d0 + 1];
            *(float2*)&r0[d0] = make_float2(acc[mt][nt][0] + b0v, acc[mt][nt][1] + b1v);
            *(float2*)&r1[d0] = make_float2(acc[mt][nt][2] + b0v, acc[mt][nt][3] + b1v);
        }
    }
}

// =============================================================================
extern "C" void kernel_launch(void* const* d_in, const int* in_sizes, int n_in,
                              void* d_out, int out_size)
{
    const float* x  = (const float*)d_in[0];
    const float* Wq = (const float*)d_in[1];
    const float* bq = (const float*)d_in[2];
    const float* Wk = (const float*)d_in[3];
    const float* bk = (const float*)d_in[4];
    const float* Wv = (const float*)d_in[5];
    const float* bv = (const float*)d_in[6];
    const float* Wo = (const float*)d_in[7];
    const float* bo = (const float*)d_in[8];
    const float* qn = (const float*)d_in[9];
    const float* kn = (const float*)d_in[10];
    float* out = (float*)d_out;

    cvtx_kernel<<<4096, 256>>>((const float4*)x);
    wtr_kernel<<<2560, 256>>>(Wq, Wk, Wv, Wo);
    qkv_kernel<<<dim3(24, 32), 128>>>(bq, bk, bv, qn, kn);
    attn_kernel<<<dim3(16, 32), 128>>>();
    out_kernel<<<dim3(16, 32), 128>>>(bo, out);
}

// round 12
// speedup vs baseline: 2.5028x; 1.0538x over previous
#include <cuda_runtime.h>
#include <cuda_fp16.h>
#include <math.h>
#include <stdint.h>

#define NTOK 2048

// ---------------- scratch (fp16 operands) ----------------
__device__ __half g_xh [(size_t)4096 * 1024];       // x       [m][k]
__device__ __half g_wqt[(size_t)1024 * 1024];       // Wq^T    [n][k]
__device__ __half g_wkt[(size_t)256  * 1024];
__device__ __half g_wvt[(size_t)256  * 1024];
__device__ __half g_wot[(size_t)1024 * 1024];
__device__ __half g_q [(size_t)2 * 16 * NTOK * 64]; // [b][h][n][d], q*(log2e/8)
__device__ __half g_k [(size_t)2 * 4  * NTOK * 64];
__device__ __half g_vt[(size_t)2 * 4  * 64 * NTOK]; // [b][kv][d][n]
__device__ __half g_o [(size_t)4096 * 1024];

__device__ __forceinline__ uint32_t PK2(float a, float b) {
    __half2 h = __floats2half2_rn(a, b);
    return *(uint32_t*)&h;
}
__device__ __forceinline__ uint32_t EX2H2(uint32_t x) {
    uint32_t y; asm("ex2.approx.f16x2 %0, %1;" : "=r"(y) : "r"(x));
    return y;
}
__device__ __forceinline__ uint32_t smem_u32(const void* p) {
    uint32_t a;
    asm("{ .reg .u64 t; cvta.to.shared.u64 t, %1; cvt.u32.u64 %0, t; }"
        : "=r"(a) : "l"(p));
    return a;
}

// D(16x8,f32) += A(16x16,f16) * B(16x8,f16)
__device__ __forceinline__ void mma16(float* d, uint32_t a0, uint32_t a1,
                                      uint32_t a2, uint32_t a3,
                                      uint32_t b0, uint32_t b1) {
    asm volatile(
        "mma.sync.aligned.m16n8k16.row.col.f32.f16.f16.f32 "
        "{%0,%1,%2,%3},{%4,%5,%6,%7},{%8,%9},{%0,%1,%2,%3};\n"
        : "+f"(d[0]), "+f"(d[1]), "+f"(d[2]), "+f"(d[3])
        : "r"(a0), "r"(a1), "r"(a2), "r"(a3), "r"(b0), "r"(b1));
}

#define LDSM4(r0, r1, r2, r3, addr) \
    asm volatile("ldmatrix.sync.aligned.m8n8.x4.shared.b16 {%0,%1,%2,%3}, [%4];" \
                 : "=r"(r0), "=r"(r1), "=r"(r2), "=r"(r3) : "r"(addr))

#define CP_ASYNC16(dst, src) \
    asm volatile("cp.async.cg.shared.global [%0], [%1], 16;\n" :: "r"(dst), "l"(src))
#define CP_COMMIT() asm volatile("cp.async.commit_group;\n" ::: "memory")
#define CP_WAIT0()  asm volatile("cp.async.wait_group 0;\n" ::: "memory")
#define CP_WAIT1()  asm volatile("cp.async.wait_group 1;\n" ::: "memory")

// =============================================================================
// Prep A: x -> fp16
// =============================================================================
__global__ __launch_bounds__(256) void cvtx_kernel(const float4* __restrict__ x)
{
    int i = blockIdx.x * 256 + threadIdx.x;   // 1048576 float4
    float4 v = x[i];
    uint2 o;
    o.x = PK2(v.x, v.y);
    o.y = PK2(v.z, v.w);
    ((uint2*)g_xh)[i] = o;
}

// =============================================================================
// Prep B: weights -> fp16 + transpose to [n][k]
// =============================================================================
__global__ __launch_bounds__(256) void wtr_kernel(
    const float* __restrict__ wq, const float* __restrict__ wk,
    const float* __restrict__ wv, const float* __restrict__ wo)
{
    __shared__ float ts[32][33];
    int t = blockIdx.x;
    const float* src; __half* dst; int N;
    if (t < 1024)      { src = wq; dst = g_wqt; N = 1024; }
    else if (t < 1280) { src = wk; dst = g_wkt; N = 256;  t -= 1024; }
    else if (t < 1536) { src = wv; dst = g_wvt; N = 256;  t -= 1280; }
    else               { src = wo; dst = g_wot; N = 1024; t -= 1536; }
    int tiles_n = N >> 5;
    int k0 = (t / tiles_n) << 5, n0 = (t % tiles_n) << 5;
    int tx = threadIdx.x & 31, ty = threadIdx.x >> 5;
    #pragma unroll
    for (int p = 0; p < 4; p++)
        ts[ty + p * 8][tx] = src[(size_t)(k0 + ty + p * 8) * N + n0 + tx];
    __syncthreads();
    #pragma unroll
    for (int p = 0; p < 4; p++)
        dst[(size_t)(n0 + ty + p * 8) * 1024 + k0 + tx] = __float2half(ts[tx][ty + p * 8]);
}

// =============================================================================
// fp16 GEMM mainloop: 128 thr / 4 warps, tile 128x64, k-step 32, 2-stage.
// =============================================================================
#define APAD 40
#define A_SZ (128 * APAD)
#define B_SZ (64 * APAD)

__device__ __forceinline__ void gemm_fp16(
    const __half* __restrict__ A, const __half* __restrict__ Bt,
    __half* sa, __half* sb, int tid, int w, int lane, float acc[2][8][4])
{
    const uint32_t as_u = smem_u32(sa);
    const uint32_t bs_u = smem_u32(sb);
    const int ldr = tid >> 2, ldc = tid & 3;

    const int m_ = lane >> 3, r_ = lane & 7;
    const uint32_t a_off = ((m_ & 1) * 8 + r_) * (APAD * 2) + (m_ >> 1) * 16;
    const uint32_t b_off = ((m_ >> 1) * 8 + r_) * (APAD * 2) + (m_ & 1) * 16;

    #pragma unroll
    for (int p = 0; p < 4; p++)
        CP_ASYNC16(as_u + ((p * 32 + ldr) * APAD) * 2 + ldc * 16,
                   &A[(size_t)(p * 32 + ldr) * 1024 + ldc * 8]);
    #pragma unroll
    for (int p = 0; p < 2; p++)
        CP_ASYNC16(bs_u + ((p * 32 + ldr) * APAD) * 2 + ldc * 16,
                   &Bt[(size_t)(p * 32 + ldr) * 1024 + ldc * 8]);
    CP_COMMIT();

    for (int i = 0; i < 32; i++) {
        const int cur = i & 1;
        if (i + 1 < 32) {
            const int nxt = 1 - cur;
            const int k0 = (i + 1) * 32;
            #pragma unroll
            for (int p = 0; p < 4; p++)
                CP_ASYNC16(as_u + (nxt * A_SZ + (p * 32 + ldr) * APAD) * 2 + ldc * 16,
                           &A[(size_t)(p * 32 + ldr) * 1024 + k0 + ldc * 8]);
            #pragma unroll
            for (int p = 0; p < 2; p++)
                CP_ASYNC16(bs_u + (nxt * B_SZ + (p * 32 + ldr) * APAD) * 2 + ldc * 16,
                           &Bt[(size_t)(p * 32 + ldr) * 1024 + k0 + ldc * 8]);
            CP_COMMIT();
            CP_WAIT1();
        } else {
            CP_WAIT0();
        }
        __syncthreads();

        const uint32_t ab = as_u + cur * A_SZ * 2;
        const uint32_t bb = bs_u + cur * B_SZ * 2;
        #pragma unroll
        for (int ks = 0; ks < 2; ks++) {
            uint32_t af[2][4];
            #pragma unroll
            for (int mt = 0; mt < 2; mt++)
                LDSM4(af[mt][0], af[mt][1], af[mt][2], af[mt][3],
                      ab + (w * 32 + mt * 16) * (APAD * 2) + ks * 32 + a_off);
            #pragma unroll
            for (int p = 0; p < 4; p++) {
                uint32_t b0a, b1a, b0b, b1b;
                LDSM4(b0a, b1a, b0b, b1b,
                      bb + (p * 16) * (APAD * 2) + ks * 32 + b_off);
                #pragma unroll
                for (int mt = 0; mt < 2; mt++) {
                    mma16(acc[mt][2 * p],     af[mt][0], af[mt][1], af[mt][2], af[mt][3], b0a, b1a);
                    mma16(acc[mt][2 * p + 1], af[mt][0], af[mt][1], af[mt][2], af[mt][3], b0b, b1b);
                }
            }
        }
        __syncthreads();
    }
}

// =============================================================================
// Kernel 1: QKV GEMM + bias + RMSNorm + 3D RoPE + q-scale (0.125*log2e)
// =============================================================================
__global__ __launch_bounds__(128) void qkv_kernel(
    const float* __restrict__ bq, const float* __restrict__ bk,
    const float* __restrict__ bv,
    const float* __restrict__ qn, const float* __restrict__ kn)
{
    __shared__ __half sa[2 * A_SZ];
    __shared__ __half sb[2 * B_SZ];
    const int tid = threadIdx.x;
    const int w = tid >> 5, lane = tid & 31, g = lane >> 2, c = lane & 3;
    const int m0 = blockIdx.y * 128;
    const int colb = blockIdx.x * 64;

    const __half* Bt; const float* bias; int seg, colloc;
    if (colb < 1024)      { Bt = g_wqt; bias = bq; seg = 0; colloc = colb; }
    else if (colb < 1280) { Bt = g_wkt; bias = bk; seg = 1; colloc = colb - 1024; }
    else                  { Bt = g_wvt; bias = bv; seg = 2; colloc = colb - 1280; }

    float acc[2][8][4] = {};
    gemm_fp16(g_xh + (size_t)m0 * 1024, Bt + (size_t)colloc * 1024,
              sa, sb, tid, w, lane, acc);

    #pragma unroll
    for (int nt = 0; nt < 8; nt++) {
        float b0v = bias[colloc + nt * 8 + 2 * c];
        float b1v = bias[colloc + nt * 8 + 2 * c + 1];
        #pragma unroll
        for (int mt = 0; mt < 2; mt++) {
            acc[mt][nt][0] += b0v; acc[mt][nt][1] += b1v;
            acc[mt][nt][2] += b0v; acc[mt][nt][3] += b1v;
        }
    }

    const int head = colloc >> 6;

    if (seg == 2) {
        #pragma unroll
        for (int mt = 0; mt < 2; mt++) {
            int m_a = m0 + w * 32 + mt * 16 + g;
            int b_ = m_a >> 11, n0 = m_a & 2047, n1 = n0 + 8;
            __half* vb = &g_vt[((size_t)(b_ * 4 + head)) * 64 * NTOK];
            #pragma unroll
            for (int nt = 0; nt < 8; nt++) {
                int d0 = nt * 8 + 2 * c;
                vb[(size_t)d0 * NTOK + n0]       = __float2half(acc[mt][nt][0]);
                vb[(size_t)(d0 + 1) * NTOK + n0] = __float2half(acc[mt][nt][1]);
                vb[(size_t)d0 * NTOK + n1]       = __float2half(acc[mt][nt][2]);
                vb[(size_t)(d0 + 1) * NTOK + n1] = __float2half(acc[mt][nt][3]);
            }
        }
        return;
    }

    // RMSNorm (intra-warp over 64-wide head dim)
    const float* nw = (seg == 0) ? qn : kn;
    #pragma unroll
    for (int mt = 0; mt < 2; mt++) {
        float ss0 = 0.f, ss1 = 0.f;
        #pragma unroll
        for (int nt = 0; nt < 8; nt++) {
            ss0 += acc[mt][nt][0] * acc[mt][nt][0] + acc[mt][nt][1] * acc[mt][nt][1];
            ss1 += acc[mt][nt][2] * acc[mt][nt][2] + acc[mt][nt][3] * acc[mt][nt][3];
        }
        ss0 += __shfl_xor_sync(~0u, ss0, 1); ss0 += __shfl_xor_sync(~0u, ss0, 2);
        ss1 += __shfl_xor_sync(~0u, ss1, 1); ss1 += __shfl_xor_sync(~0u, ss1, 2);
        float rs0 = rsqrtf(ss0 * (1.f / 64.f) + 1e-6f);
        float rs1 = rsqrtf(ss1 * (1.f / 64.f) + 1e-6f);
        #pragma unroll
        for (int nt = 0; nt < 8; nt++) {
            float w0 = nw[nt * 8 + 2 * c], w1 = nw[nt * 8 + 2 * c + 1];
            acc[mt][nt][0] *= rs0 * w0; acc[mt][nt][1] *= rs0 * w1;
            acc[mt][nt][2] *= rs1 * w0; acc[mt][nt][3] *= rs1 * w1;
        }
    }

    // 3D RoPE in-place: pairs t:(0,1) h:(2,3) w:(4,6),(5,7)
    const int lo_[4] = {0, 2, 4, 5};
    const int hi_[4] = {1, 3, 6, 7};
    #pragma unroll
    for (int mt = 0; mt < 2; mt++) {
        int m_a = m0 + w * 32 + mt * 16 + g;
        int n0 = m_a & 2047, n1 = n0 + 8;
        float posr[2][3] = {
            {(float)(n0 >> 8), (float)((n0 >> 4) & 15), (float)(n0 & 15)},
            {(float)(n1 >> 8), (float)((n1 >> 4) & 15), (float)(n1 & 15)}};
        #pragma unroll
        for (int pi = 0; pi < 4; pi++) {
            int lo = lo_[pi], hi = hi_[pi];
            int ax = (pi == 0) ? 0 : (pi == 1 ? 1 : 2);
            float halfinv = (pi < 2) ? (1.f / 8.f) : (1.f / 16.f);
            #pragma unroll
            for (int e = 0; e < 2; e++) {
                float f = (pi < 2) ? (float)(2 * c + e)
                                   : (float)((lo & 1) * 8 + 2 * c + e);
                float inv = __powf(10000.f, -f * halfinv);
                #pragma unroll
                for (int r = 0; r < 2; r++) {
                    float sv, cv;
                    __sincosf(posr[r][ax] * inv, &sv, &cv);
                    float xl = acc[mt][lo][2 * r + e];
                    float xh = acc[mt][hi][2 * r + e];
                    acc[mt][lo][2 * r + e] = xl * cv - xh * sv;
                    acc[mt][hi][2 * r + e] = xh * cv + xl * sv;
                }
            }
        }
    }

    float sc = (seg == 0) ? (0.125f * 1.4426950408889634f) : 1.f;
    #pragma unroll
    for (int mt = 0; mt < 2; mt++) {
        int m_a = m0 + w * 32 + mt * 16 + g;
        int b_ = m_a >> 11, n0 = m_a & 2047, n1 = n0 + 8;
        __half* qb = (seg == 0) ? &g_q[((size_t)(b_ * 16 + head)) * NTOK * 64]
                                : &g_k[((size_t)(b_ * 4 + head)) * NTOK * 64];
        #pragma unroll
        for (int nt = 0; nt < 8; nt++) {
            int d0 = nt * 8 + 2 * c;
            *(uint32_t*)&qb[(size_t)n0 * 64 + d0] = PK2(acc[mt][nt][0] * sc, acc[mt][nt][1] * sc);
            *(uint32_t*)&qb[(size_t)n1 * 64 + d0] = PK2(acc[mt][nt][2] * sc, acc[mt][nt][3] * sc);
        }
    }
}

// =============================================================================
// Kernel 2: flash attention fp16. 128 thr / 4 warps, warp M=32, q-block 128.
//   ex2.approx.f16x2 softmax (P emerges fp16-packed); row sums via ones-mma;
//   no shuffles; K+V double-buffered cp.async; ldmatrix frags.
// =============================================================================
#define KVP 72
#define H2_ONES 0x3C003C00u

__global__ __launch_bounds__(128, 3) void attn_kernel()
{
    __shared__ __half kvs[2][2][64 * KVP];   // [buf][K/V][...]

    const int tid = threadIdx.x;
    const int w = tid >> 5, lane = tid & 31, g = lane >> 2, c = lane & 3;
    const int q0 = blockIdx.x * 128;
    const int bh = blockIdx.y;
    const int b_ = bh >> 4, h = bh & 15, kv = h >> 2;

    const __half* qg = &g_q[((size_t)(b_ * 16 + h)) * NTOK * 64];
    const __half* kg = &g_k[((size_t)(b_ * 4 + kv)) * NTOK * 64];
    const __half* vg = &g_vt[((size_t)(b_ * 4 + kv)) * 64 * NTOK];

    const int lr = tid >> 1, lc = tid & 1;
    const uint32_t k_u = smem_u32(&kvs[0][0][0]) + lr * (KVP * 2) + lc * 64;
    const uint32_t v_u = smem_u32(&kvs[0][1][0]) + lr * (KVP * 2) + lc * 64;
    const uint32_t bufstride = 2 * 64 * KVP * 2;

    const int m_ = lane >> 3, r_ = lane & 7;
    const uint32_t b_off = ((m_ >> 1) * 8 + r_) * (KVP * 2) + (m_ & 1) * 16;
    const uint32_t kbase = smem_u32(&kvs[0][0][0]) + b_off;
    const uint32_t vbase = smem_u32(&kvs[0][1][0]) + b_off;

    // Q fragments register-resident
    uint32_t qf[2][4][4];
    {
        const __half* r0 = &qg[(size_t)(q0 + w * 32 + g) * 64];
        #pragma unroll
        for (int mt = 0; mt < 2; mt++)
            #pragma unroll
            for (int kc = 0; kc < 4; kc++) {
                qf[mt][kc][0] = *(const uint32_t*)&r0[mt * 16 * 64 + kc * 16 + 2 * c];
                qf[mt][kc][1] = *(const uint32_t*)&r0[(mt * 16 + 8) * 64 + kc * 16 + 2 * c];
                qf[mt][kc][2] = *(const uint32_t*)&r0[mt * 16 * 64 + kc * 16 + 8 + 2 * c];
                qf[mt][kc][3] = *(const uint32_t*)&r0[(mt * 16 + 8) * 64 + kc * 16 + 8 + 2 * c];
            }
    }

    float o[2][8][4] = {};
    float lpa[2][4] = {};   // row-sum accumulators via ones-mma

    // prologue: K0 + V0
    #pragma unroll
    for (int i = 0; i < 4; i++) {
        CP_ASYNC16(k_u + i * 16, &kg[(size_t)lr * 64 + lc * 32 + i * 8]);
        CP_ASYNC16(v_u + i * 16, &vg[(size_t)lr * NTOK + lc * 32 + i * 8]);
    }
    CP_COMMIT();

    for (int kt = 0; kt < NTOK; kt += 64) {
        const int buf = (kt >> 6) & 1;
        CP_WAIT0();
        __syncthreads();

        if (kt + 64 < NTOK) {
            const uint32_t off = (1 - buf) * bufstride;
            #pragma unroll
            for (int i = 0; i < 4; i++) {
                CP_ASYNC16(k_u + off + i * 16, &kg[(size_t)(kt + 64 + lr) * 64 + lc * 32 + i * 8]);
                CP_ASYNC16(v_u + off + i * 16, &vg[(size_t)lr * NTOK + kt + 64 + lc * 32 + i * 8]);
            }
            CP_COMMIT();
        }

        const uint32_t kb = kbase + buf * bufstride;
        const uint32_t vb = vbase + buf * bufstride;

        // S = Q K^T
        float s[2][8][4] = {};
        #pragma unroll
        for (int kc = 0; kc < 4; kc++) {
            #pragma unroll
            for (int p = 0; p < 4; p++) {
                uint32_t b0a, b1a, b0b, b1b;
                LDSM4(b0a, b1a, b0b, b1b, kb + p * 16 * (KVP * 2) + kc * 32);
                #pragma unroll
                for (int mt = 0; mt < 2; mt++) {
                    mma16(s[mt][2 * p],     qf[mt][kc][0], qf[mt][kc][1], qf[mt][kc][2], qf[mt][kc][3], b0a, b1a);
                    mma16(s[mt][2 * p + 1], qf[mt][kc][0], qf[mt][kc][1], qf[mt][kc][2], qf[mt][kc][3], b0b, b1b);
                }
            }
        }

        // P = 2^S: pack to half2 then one ex2.f16x2 per pair (P ends fp16-packed)
        uint32_t pa[2][4][4];
        #pragma unroll
        for (int mt = 0; mt < 2; mt++)
            #pragma unroll
            for (int kc = 0; kc < 4; kc++) {
                pa[mt][kc][0] = EX2H2(PK2(s[mt][2 * kc][0],     s[mt][2 * kc][1]));
                pa[mt][kc][1] = EX2H2(PK2(s[mt][2 * kc][2],     s[mt][2 * kc][3]));
                pa[mt][kc][2] = EX2H2(PK2(s[mt][2 * kc + 1][0], s[mt][2 * kc + 1][1]));
                pa[mt][kc][3] = EX2H2(PK2(s[mt][2 * kc + 1][2], s[mt][2 * kc + 1][3]));
            }

        // row sums: P @ ones (every output col = row sum over this kc's 16 keys)
        #pragma unroll
        for (int mt = 0; mt < 2; mt++)
            #pragma unroll
            for (int kc = 0; kc < 4; kc++)
                mma16(lpa[mt], pa[mt][kc][0], pa[mt][kc][1], pa[mt][kc][2], pa[mt][kc][3],
                      H2_ONES, H2_ONES);

        // O += P V
        #pragma unroll
        for (int kc = 0; kc < 4; kc++) {
            #pragma unroll
            for (int p = 0; p < 4; p++) {
                uint32_t b0a, b1a, b0b, b1b;
                LDSM4(b0a, b1a, b0b, b1b, vb + p * 16 * (KVP * 2) + kc * 32);
                #pragma unroll
                for (int mt = 0; mt < 2; mt++) {
                    mma16(o[mt][2 * p],     pa[mt][kc][0], pa[mt][kc][1], pa[mt][kc][2], pa[mt][kc][3], b0a, b1a);
                    mma16(o[mt][2 * p + 1], pa[mt][kc][0], pa[mt][kc][1], pa[mt][kc][2], pa[mt][kc][3], b0b, b1b);
                }
            }
        }
    }

    #pragma unroll
    for (int mt = 0; mt < 2; mt++) {
        float inv0 = 1.f / lpa[mt][0], inv1 = 1.f / lpa[mt][2];
        int n0 = q0 + w * 32 + mt * 16 + g, n1 = n0 + 8;
        __half* ob0 = &g_o[((size_t)(b_ * NTOK + n0)) * 1024 + h * 64];
        __half* ob1 = &g_o[((size_t)(b_ * NTOK + n1)) * 1024 + h * 64];
        #pragma unroll
        for (int nt = 0; nt < 8; nt++) {
            int d0 = nt * 8 + 2 * c;
            *(uint32_t*)&ob0[d0] = PK2(o[mt][nt][0] * inv0, o[mt][nt][1] * inv0);
            *(uint32_t*)&ob1[d0] = PK2(o[mt][nt][2] * inv1, o[mt][nt][3] * inv1);
        }
    }
}

// =============================================================================
// Kernel 3: out = O @ Wo + bo  (fp16 operands, fp32 out)
// =============================================================================
__global__ __launch_bounds__(128) void out_kernel(
    const float* __restrict__ bo, float* __restrict__ out)
{
    __shared__ __half sa[2 * A_SZ];
    __shared__ __half sb[2 * B_SZ];
    const int tid = threadIdx.x;
    const int w = tid >> 5, lane = tid & 31, g = lane >> 2, c = lane & 3;
    const int m0 = blockIdx.y * 128;
    const int colb = blockIdx.x * 64;

    float acc[2][8][4] = {};
    gemm_fp16(g_o + (size_t)m0 * 1024, g_wot + (size_t)colb * 1024,
              sa, sb, tid, w, lane, acc);

    #pragma unroll
    for (int mt = 0; mt < 2; mt++) {
        int m_a = m0 + w * 32 + mt * 16 + g;
        float* r0 = &out[(size_t)m_a * 1024 + colb];
        float* r1 = &out[(size_t)(m_a + 8) * 1024 + colb];
        #pragma unroll
        for (int nt = 0; nt < 8; nt++) {
            int d0 = nt * 8 + 2 * c;
            float b0v = bo[colb + d0], b1v = bo[colb + d0 + 1];
            *(float2*)&r0[d0] = make_float2(acc[mt][nt][0] + b0v, acc[mt][nt][1] + b1v);
            *(float2*)&r1[d0] = make_float2(acc[mt][nt][2] + b0v, acc[mt][nt][3] + b1v);
        }
    }
}

// =============================================================================
extern "C" void kernel_launch(void* const* d_in, const int* in_sizes, int n_in,
                              void* d_out, int out_size)
{
    const float* x  = (const float*)d_in[0];
    const float* Wq = (const float*)d_in[1];
    const float* bq = (const float*)d_in[2];
    const float* Wk = (const float*)d_in[3];
    const float* bk = (const float*)d_in[4];
    const float* Wv = (const float*)d_in[5];
    const float* bv = (const float*)d_in[6];
    const float* Wo = (const float*)d_in[7];
    const float* bo = (const float*)d_in[8];
    const float* qn = (const float*)d_in[9];
    const float* kn = (const float*)d_in[10];
    float* out = (float*)d_out;

    cvtx_kernel<<<4096, 256>>>((const float4*)x);
    wtr_kernel<<<2560, 256>>>(Wq, Wk, Wv, Wo);
    qkv_kernel<<<dim3(24, 32), 128>>>(bq, bk, bv, qn, kn);
    attn_kernel<<<dim3(16, 32), 128>>>();
    out_kernel<<<dim3(16, 32), 128>>>(bo, out);
}